// round 11
// baseline (speedup 1.0000x reference)
#include <cuda_runtime.h>
#include <cuda_bf16.h>
#include <stdint.h>
#include <math.h>

#define BB 256     // batch
#define HH 512     // hidden
#define VV 100     // vocab
#define TT 200     // steps

// fp32 hidden-state history (proj + epilogue need fp32 h)
__device__ float g_hist[(size_t)TT * BB * HH];
// bf16 hi/lo ping-pong of previous hidden state
__device__ __nv_bfloat16 g_hh[2][BB * HH];
__device__ __nv_bfloat16 g_hl[2][BB * HH];
// packed weights: row n = jb*96 + g*16 + j  (jb=0..31, g=0..5, j=0..15), k=0..511
__device__ __nv_bfloat16 g_wh[6 * HH * HH];
__device__ __nv_bfloat16 g_wl[6 * HH * HH];
// per-batch-group step barrier counters
__device__ unsigned int g_ctrs[4];

__device__ __forceinline__ float sigmoidf_(float x) {
    return 1.0f / (1.0f + expf(-x));
}
// fast epilogue math (MUFU-based)
__device__ __forceinline__ float fast_sig(float x) {
    return 1.0f / (1.0f + __expf(-x));
}
__device__ __forceinline__ float fast_tanh(float x) {
    return 2.0f / (1.0f + __expf(-2.0f * x)) - 1.0f;
}

// ---------------------------------------------------------------------------
// async / mma / sync helpers
// ---------------------------------------------------------------------------
__device__ __forceinline__ void cp_async16(void* smem_dst, const void* gmem_src) {
    unsigned int s = (unsigned int)__cvta_generic_to_shared(smem_dst);
    asm volatile("cp.async.cg.shared.global [%0], [%1], 16;\n" :: "r"(s), "l"(gmem_src));
}
#define CP_COMMIT() asm volatile("cp.async.commit_group;\n" ::: "memory")
#define CP_WAIT(n)  asm volatile("cp.async.wait_group %0;\n" :: "n"(n) : "memory")

__device__ __forceinline__ void ldsm4(uint32_t r[4], const void* p) {
    unsigned int s = (unsigned int)__cvta_generic_to_shared(p);
    asm volatile("ldmatrix.sync.aligned.m8n8.x4.shared.b16 {%0,%1,%2,%3}, [%4];"
                 : "=r"(r[0]), "=r"(r[1]), "=r"(r[2]), "=r"(r[3]) : "r"(s));
}

__device__ __forceinline__ void mma_bf16(float d[4], const uint32_t a[4],
                                         uint32_t b0, uint32_t b1) {
    asm volatile(
        "mma.sync.aligned.m16n8k16.row.col.f32.bf16.bf16.f32 "
        "{%0,%1,%2,%3}, {%4,%5,%6,%7}, {%8,%9}, {%0,%1,%2,%3};"
        : "+f"(d[0]), "+f"(d[1]), "+f"(d[2]), "+f"(d[3])
        : "r"(a[0]), "r"(a[1]), "r"(a[2]), "r"(a[3]), "r"(b0), "r"(b1));
}

__device__ __forceinline__ unsigned int ld_acq(const unsigned int* p) {
    unsigned int v;
    asm volatile("ld.acquire.gpu.u32 %0, [%1];" : "=r"(v) : "l"(p));
    return v;
}

// ---------------------------------------------------------------------------
// One-time weight prep: pack + split fp32 -> bf16 hi/lo.
// ---------------------------------------------------------------------------
__global__ __launch_bounds__(256) void prep_weights(
    const float* __restrict__ w_ih, const float* __restrict__ w_hh)
{
    int idx = blockIdx.x * 256 + threadIdx.x;
    if (idx >= 6 * HH * HH) return;
    int n = idx / HH, k = idx % HH;
    int jb = n / 96, rr = n % 96, g = rr / 16, j = rr % 16;
    const float* src = (g < 3) ? w_ih : w_hh;
    float v = src[(size_t)((g % 3) * HH + jb * 16 + j) * HH + k];
    __nv_bfloat16 hi = __float2bfloat16(v);
    g_wh[idx] = hi;
    g_wl[idx] = __float2bfloat16(v - __bfloat162float(hi));
}

__global__ void reset_ctr_kernel() {
    if (threadIdx.x < 4) g_ctrs[threadIdx.x] = 0u;
}

// ---------------------------------------------------------------------------
// Convert fp32 h -> bf16 hi/lo (after step 0)
// ---------------------------------------------------------------------------
__global__ __launch_bounds__(256) void convert_h(
    const float* __restrict__ h, __nv_bfloat16* __restrict__ hh,
    __nv_bfloat16* __restrict__ hl)
{
    int idx = blockIdx.x * 256 + threadIdx.x;
    if (idx >= BB * HH) return;
    float v = h[idx];
    __nv_bfloat16 hi = __float2bfloat16(v);
    hh[idx] = hi;
    hl[idx] = __float2bfloat16(v - __bfloat162float(hi));
}

// ---------------------------------------------------------------------------
// Persistent tensor-core GRU, v5: R7 skeleton + single-sync chunk loop +
// batched fragment loads. Grid (32 jb, 4 bq) = 128 blocks, 384 threads
// (12 warps: 4 mw x 3 nv(n=32)). B tile XOR-swizzled, SMEM-resident.
// A streamed per step, k=64 chunks, double buffer, ONE bar.sync per chunk.
// ---------------------------------------------------------------------------
#define THR    384
#define B_MATS (96 * 512)                   // bf16 per B matrix (swizzled, no pad)
#define OFF_A  (2 * B_MATS)                 // 98304 bf16
#define A_MATS (64 * 64)                    // bf16 per A matrix per chunk (k=64)
#define A_BUF  (2 * A_MATS)                 // hi+lo per buffer = 8192 bf16
#define SMEM_P ((OFF_A + 2 * A_BUF) * 2)    // 229376 bytes (224 KB)
#define NCH    8                            // K chunks of 64

__global__ __launch_bounds__(THR) void gru_persistent(
    const float* __restrict__ b_ih,
    const float* __restrict__ b_hh,
    float* __restrict__ hist,                 // [TT][BB][HH]
    __nv_bfloat16* __restrict__ hh_base,      // [2][BB*HH]
    __nv_bfloat16* __restrict__ hl_base)
{
    extern __shared__ __align__(16) __nv_bfloat16 dsm[];

    const int tid  = threadIdx.x;
    const int lane = tid & 31;
    const int w    = tid >> 5;           // 0..11
    const int mw   = w & 3;              // m16 tile
    const int nv   = w >> 2;             // 0..2, n=32 each
    const int jb   = blockIdx.x;         // 0..31
    const int bq   = blockIdx.y;         // 0..3
    const int b0   = bq * 64;

    // ================= resident B load (swizzled, once) =================
    for (int i = tid; i < 2 * 96 * 64; i += THR) {     // 16B granules
        const int mat = i / (96 * 64);
        const int rr  = i % (96 * 64);
        const int row = rr >> 6;
        const int g   = rr & 63;
        const int gs  = (g & 56) | ((g ^ row) & 7);
        const __nv_bfloat16* src =
            (mat ? g_wl : g_wh) + (size_t)(jb * 96 + row) * HH + g * 8;
        cp_async16(dsm + mat * B_MATS + row * 512 + gs * 8, src);
    }
    CP_COMMIT();

    // ========== per-thread A-chunk cp.async descriptors (<=3 each) =========
    int aMat[3], aDst[3], aSrc[3];
    #pragma unroll
    for (int k = 0; k < 3; k++) {
        const int i = tid + THR * k;
        if (i < 1024) {
            const int mat = i >> 9;
            const int r   = (i >> 3) & 63;
            const int g   = i & 7;
            aMat[k] = mat;
            aDst[k] = mat * A_MATS + r * 64 + ((g ^ (r & 7)) * 8);
            aSrc[k] = (b0 + r) * HH + g * 8;
        }
    }
    const bool a3 = (tid + 2 * THR < 1024);

    // ================= ldmatrix lane invariants =================
    const int a_row  = mw * 16 + (lane & 15);
    const int a_g0   = (lane >> 4);
    const int a_base = a_row * 64;
    const int a_r7   = a_row & 7;
    const int b_rowL = (lane & 7) + ((lane & 16) ? 8 : 0);
    const int b_g0   = (lane & 8) ? 1 : 0;
    int b_base[2], b_r7[2];
    #pragma unroll
    for (int p = 0; p < 2; p++) {
        const int brow = nv * 32 + p * 16 + b_rowL;
        b_base[p] = brow * 512;
        b_r7[p]   = brow & 7;
    }
    const int r_base = mw * 16 + (lane >> 2);

    // ================= epilogue per-thread state =================
    float hp[3], br_[3], bz_[3], bni_[3], bnh_[3];
    int   ooff[3];
    #pragma unroll
    for (int n = 0; n < 3; n++) {
        const int e = tid + THR * n;
        if (e < 1024) {
            const int b  = e >> 4;
            const int j  = e & 15;
            const int jg = jb * 16 + j;
            ooff[n] = (b0 + b) * HH + jg;
            br_[n]  = b_ih[jg] + b_hh[jg];
            bz_[n]  = b_ih[HH + jg] + b_hh[HH + jg];
            bni_[n] = b_ih[2 * HH + jg];
            bnh_[n] = b_hh[2 * HH + jg];
            hp[n]   = hist[ooff[n]];
        }
    }

    CP_WAIT(0);
    __syncthreads();

    float acc[4][4];
    #pragma unroll
    for (int f = 0; f < 4; f++)
        #pragma unroll
        for (int i = 0; i < 4; i++) acc[f][i] = 0.0f;

    float* sG = (float*)(dsm + OFF_A);   // [64][100] gate exchange (aliases A)

    for (int t = 1; t < TT; t++) {
        const __nv_bfloat16* srcH = hh_base + (size_t)((t - 1) & 1) * BB * HH;
        const __nv_bfloat16* srcL = hl_base + (size_t)((t - 1) & 1) * BB * HH;

        // prologue: chunk 0 -> buf 0 (post-epilogue sync of step t-1 protects)
        {
            __nv_bfloat16* buf = dsm + OFF_A;
            cp_async16(buf + aDst[0], (aMat[0] ? srcL : srcH) + aSrc[0]);
            cp_async16(buf + aDst[1], (aMat[1] ? srcL : srcH) + aSrc[1]);
            if (a3)
                cp_async16(buf + aDst[2], (aMat[2] ? srcL : srcH) + aSrc[2]);
            CP_COMMIT();
        }

        // ---- chunk loop: ONE sync per chunk ----
        #pragma unroll 1
        for (int c = 0; c < NCH; c++) {
            CP_WAIT(0);            // chunk c landed (only group outstanding)
            __syncthreads();       // all warps: data visible, chunk c-1 reads done

            const __nv_bfloat16* bufA = dsm + OFF_A + (c & 1) * A_BUF;

            // ---- batch-load ALL fragments of this chunk ----
            uint32_t fAH[4][4], fAL[4][4], fBH[4][2][4], fBL[4][2][4];
            #pragma unroll
            for (int q = 0; q < 4; q++) {
                const int gsA = ((2 * q + a_g0) ^ a_r7) * 8;
                ldsm4(fAH[q], bufA + a_base + gsA);
                ldsm4(fAL[q], bufA + A_MATS + a_base + gsA);
                const int gqB = c * 8 + 2 * q + b_g0;
                #pragma unroll
                for (int p = 0; p < 2; p++) {
                    const int gsB = (gqB & 56) | ((gqB ^ b_r7[p]) & 7);
                    const int off = b_base[p] + gsB * 8;
                    ldsm4(fBH[q][p], dsm + off);
                    ldsm4(fBL[q][p], dsm + B_MATS + off);
                }
            }

            // ---- prefetch chunk c+1 (safe: sync(c) passed by all warps) ----
            if (c + 1 < NCH) {
                __nv_bfloat16* buf = dsm + OFF_A + ((c + 1) & 1) * A_BUF;
                const int k0 = (c + 1) * 64;
                cp_async16(buf + aDst[0], (aMat[0] ? srcL : srcH) + aSrc[0] + k0);
                cp_async16(buf + aDst[1], (aMat[1] ? srcL : srcH) + aSrc[1] + k0);
                if (a3)
                    cp_async16(buf + aDst[2], (aMat[2] ? srcL : srcH) + aSrc[2] + k0);
                CP_COMMIT();
            }

            // ---- MMAs: interleaved accumulator chains ----
            #pragma unroll
            for (int q = 0; q < 4; q++) {
                #pragma unroll
                for (int p = 0; p < 2; p++) {
                    mma_bf16(acc[2 * p],     fAH[q], fBH[q][p][0], fBH[q][p][1]);
                    mma_bf16(acc[2 * p + 1], fAH[q], fBH[q][p][2], fBH[q][p][3]);
                }
                #pragma unroll
                for (int p = 0; p < 2; p++) {
                    mma_bf16(acc[2 * p],     fAH[q], fBL[q][p][0], fBL[q][p][1]);
                    mma_bf16(acc[2 * p + 1], fAH[q], fBL[q][p][2], fBL[q][p][3]);
                }
                #pragma unroll
                for (int p = 0; p < 2; p++) {
                    mma_bf16(acc[2 * p],     fAL[q], fBH[q][p][0], fBH[q][p][1]);
                    mma_bf16(acc[2 * p + 1], fAL[q], fBH[q][p][2], fBH[q][p][3]);
                }
            }
        }
        __syncthreads();   // all chunk-7 reads done before sG overwrite

        // ---- write fragments to sG[64][100] ----
        {
            #pragma unroll
            for (int f = 0; f < 4; f++) {
                const int cb = nv * 32 + f * 8 + (lane & 3) * 2;
                sG[r_base * 100 + cb]           = acc[f][0];
                sG[r_base * 100 + cb + 1]       = acc[f][1];
                sG[(r_base + 8) * 100 + cb]     = acc[f][2];
                sG[(r_base + 8) * 100 + cb + 1] = acc[f][3];
            }
        }
        __syncthreads();

        // ---- gate epilogue (fast MUFU math) ----
        {
            __nv_bfloat16* dstH = hh_base + (size_t)(t & 1) * BB * HH;
            __nv_bfloat16* dstL = hl_base + (size_t)(t & 1) * BB * HH;
            float* hout = hist + (size_t)t * BB * HH;
            #pragma unroll
            for (int n = 0; n < 3; n++) {
                const int e = tid + THR * n;
                if (e < 1024) {
                    const int b = e >> 4, j = e & 15;
                    const float gr = sG[b * 100 + j];
                    const float gz = sG[b * 100 + 16 + j];
                    const float gn = sG[b * 100 + 32 + j];
                    const float hr = sG[b * 100 + 48 + j];
                    const float hz = sG[b * 100 + 64 + j];
                    const float hn = sG[b * 100 + 80 + j];
                    const float rv = fast_sig(gr + hr + br_[n]);
                    const float zv = fast_sig(gz + hz + bz_[n]);
                    const float nn = fast_tanh(gn + bni_[n] + rv * (hn + bnh_[n]));
                    const float hv = (1.0f - zv) * nn + zv * hp[n];
                    hp[n] = hv;
                    hout[ooff[n]] = hv;
                    const __nv_bfloat16 hi = __float2bfloat16(hv);
                    dstH[ooff[n]] = hi;
                    dstL[ooff[n]] = __float2bfloat16(hv - __bfloat162float(hi));
                }
            }
        }
        __threadfence();

        // reset accumulators
        #pragma unroll
        for (int f = 0; f < 4; f++)
            #pragma unroll
            for (int i = 0; i < 4; i++) acc[f][i] = 0.0f;

        __syncthreads();   // epilogue stores + sG reads done

        // ---- per-group grid barrier (R7 form; skip after final step) ----
        if (t < TT - 1) {
            if (tid == 0) {
                atomicAdd(&g_ctrs[bq], 1u);
                const unsigned int target = (unsigned int)t * 32u;
                unsigned int v;
                do {
                    v = ld_acq(&g_ctrs[bq]);
                } while (v < target);
            }
            __syncthreads();
        }
    }
}

// ---------------------------------------------------------------------------
// Generic fp32 GRU step — used only for t = 0 (x = embed row, h = feat).
// ---------------------------------------------------------------------------
__global__ __launch_bounds__(256) void gru_step_kernel(
    const float* __restrict__ x, int xs,
    const float* __restrict__ h,
    const float* __restrict__ w_ih,
    const float* __restrict__ w_hh,
    const float* __restrict__ b_ih,
    const float* __restrict__ b_hh,
    float* __restrict__ h_out)
{
    __shared__ float sX[32][32];
    __shared__ float sH[32][32];
    __shared__ float sWih[3][32][32];
    __shared__ float sWhh[3][32][32];

    const int tid = threadIdx.x;
    const int tj  = tid & 31;
    const int tb  = tid >> 5;
    const int j0  = blockIdx.x * 32;
    const int b0  = blockIdx.y * 32;

    float acc[4][6];
    #pragma unroll
    for (int i = 0; i < 4; i++)
        #pragma unroll
        for (int g = 0; g < 6; g++) acc[i][g] = 0.0f;

    const int lb  = tid >> 3;
    const int lk4 = (tid & 7) * 4;

    for (int k0 = 0; k0 < HH; k0 += 32) {
        float4 xv4 = *(const float4*)(x + (size_t)(b0 + lb) * (size_t)xs + k0 + lk4);
        *(float4*)&sX[lb][lk4] = xv4;
        float4 hv4 = *(const float4*)(h + (size_t)(b0 + lb) * HH + k0 + lk4);
        *(float4*)&sH[lb][lk4] = hv4;
        #pragma unroll
        for (int g = 0; g < 3; g++) {
            float4 wi = *(const float4*)(w_ih + (size_t)(g * HH + j0 + lb) * HH + k0 + lk4);
            sWih[g][lk4 + 0][lb] = wi.x;
            sWih[g][lk4 + 1][lb] = wi.y;
            sWih[g][lk4 + 2][lb] = wi.z;
            sWih[g][lk4 + 3][lb] = wi.w;
            float4 wh = *(const float4*)(w_hh + (size_t)(g * HH + j0 + lb) * HH + k0 + lk4);
            sWhh[g][lk4 + 0][lb] = wh.x;
            sWhh[g][lk4 + 1][lb] = wh.y;
            sWhh[g][lk4 + 2][lb] = wh.z;
            sWhh[g][lk4 + 3][lb] = wh.w;
        }
        __syncthreads();

        #pragma unroll
        for (int kk = 0; kk < 32; kk++) {
            const float wi0 = sWih[0][kk][tj];
            const float wi1 = sWih[1][kk][tj];
            const float wi2 = sWih[2][kk][tj];
            const float wh0 = sWhh[0][kk][tj];
            const float wh1 = sWhh[1][kk][tj];
            const float wh2 = sWhh[2][kk][tj];
            #pragma unroll
            for (int i = 0; i < 4; i++) {
                const float xv = sX[tb * 4 + i][kk];
                const float hv = sH[tb * 4 + i][kk];
                acc[i][0] += xv * wi0;
                acc[i][1] += xv * wi1;
                acc[i][2] += xv * wi2;
                acc[i][3] += hv * wh0;
                acc[i][4] += hv * wh1;
                acc[i][5] += hv * wh2;
            }
        }
        __syncthreads();
    }

    const int j = j0 + tj;
    const float bir  = b_ih[j],          bhr = b_hh[j];
    const float biz  = b_ih[HH + j],     bhz = b_hh[HH + j];
    const float bin_ = b_ih[2 * HH + j], bhn = b_hh[2 * HH + j];
    #pragma unroll
    for (int i = 0; i < 4; i++) {
        const int b = b0 + tb * 4 + i;
        const float r = sigmoidf_(acc[i][0] + bir + acc[i][3] + bhr);
        const float z = sigmoidf_(acc[i][1] + biz + acc[i][4] + bhz);
        const float n = tanhf(acc[i][2] + bin_ + r * (acc[i][5] + bhn));
        const float hp = h[(size_t)b * HH + j];
        h_out[(size_t)b * HH + j] = (1.0f - z) * n + z * hp;
    }
}

// ---------------------------------------------------------------------------
// Projection: out[b][v][t] = hist[t][b][:] . proj_w[v][:] + proj_b[v]
// ---------------------------------------------------------------------------
__global__ __launch_bounds__(512) void proj_kernel(
    const float* __restrict__ proj_w,
    const float* __restrict__ proj_b,
    float* __restrict__ out)
{
    __shared__ float sH[TT][33];
    __shared__ float sW[VV][33];

    const int b   = blockIdx.x;
    const int tid = threadIdx.x;
    const int tg  = tid % 25;
    const int vg  = tid / 25;
    const bool active = (tid < 500);

    float acc[8][5];
    #pragma unroll
    for (int i = 0; i < 8; i++)
        #pragma unroll
        for (int jv = 0; jv < 5; jv++) acc[i][jv] = 0.0f;

    for (int k0 = 0; k0 < HH; k0 += 32) {
        for (int idx = tid; idx < TT * 32; idx += 512) {
            const int t = idx >> 5, k = idx & 31;
            sH[t][k] = g_hist[((size_t)t * BB + b) * HH + k0 + k];
        }
        for (int idx = tid; idx < VV * 32; idx += 512) {
            const int v = idx >> 5, k = idx & 31;
            sW[v][k] = proj_w[(size_t)v * HH + k0 + k];
        }
        __syncthreads();

        if (active) {
            #pragma unroll
            for (int kk = 0; kk < 32; kk++) {
                float wv[5];
                #pragma unroll
                for (int jv = 0; jv < 5; jv++) wv[jv] = sW[vg * 5 + jv][kk];
                #pragma unroll
                for (int i = 0; i < 8; i++) {
                    const float hv = sH[tg + 25 * i][kk];
                    #pragma unroll
                    for (int jv = 0; jv < 5; jv++) acc[i][jv] += hv * wv[jv];
                }
            }
        }
        __syncthreads();
    }

    if (active) {
        float pb[5];
        #pragma unroll
        for (int jv = 0; jv < 5; jv++) pb[jv] = proj_b[vg * 5 + jv];
        #pragma unroll
        for (int i = 0; i < 8; i++) {
            const int t = tg + 25 * i;
            #pragma unroll
            for (int jv = 0; jv < 5; jv++) {
                const int v = vg * 5 + jv;
                out[((size_t)b * VV + v) * TT + t] = acc[i][jv] + pb[jv];
            }
        }
    }
}

// ---------------------------------------------------------------------------
extern "C" void kernel_launch(void* const* d_in, const int* in_sizes, int n_in,
                              void* d_out, int out_size)
{
    (void)in_sizes; (void)n_in; (void)out_size;
    const float* feat   = (const float*)d_in[0];
    const float* embed  = (const float*)d_in[1];
    const float* w_ih   = (const float*)d_in[2];
    const float* w_hh   = (const float*)d_in[3];
    const float* b_ih   = (const float*)d_in[4];
    const float* b_hh   = (const float*)d_in[5];
    const float* proj_w = (const float*)d_in[6];
    const float* proj_b = (const float*)d_in[7];
    float* out = (float*)d_out;

    float* hist = nullptr;
    cudaGetSymbolAddress((void**)&hist, g_hist);
    __nv_bfloat16* hhp = nullptr;
    cudaGetSymbolAddress((void**)&hhp, g_hh);
    __nv_bfloat16* hlp = nullptr;
    cudaGetSymbolAddress((void**)&hlp, g_hl);

    cudaFuncSetAttribute(gru_persistent,
                         cudaFuncAttributeMaxDynamicSharedMemorySize, SMEM_P);

    prep_weights<<<(6 * HH * HH + 255) / 256, 256>>>(w_ih, w_hh);
    reset_ctr_kernel<<<1, 32>>>();

    // step 0: x = embed[SOS=0] broadcast, h = feat  -> hist[0]
    gru_step_kernel<<<dim3(HH / 32, BB / 32), 256>>>(embed, 0, feat,
                                                     w_ih, w_hh, b_ih, b_hh, hist);
    convert_h<<<(BB * HH + 255) / 256, 256>>>(hist, hhp, hlp);   // -> pp slot 0

    // steps 1..199: persistent tensor-core kernel (one wave of 128 blocks)
    gru_persistent<<<dim3(32, 4), THR, SMEM_P>>>(b_ih, b_hh, hist, hhp, hlp);

    proj_kernel<<<BB, 512>>>(proj_w, proj_b, out);
}

// round 12
// speedup vs baseline: 1.1555x; 1.1555x over previous
#include <cuda_runtime.h>
#include <cuda_bf16.h>
#include <stdint.h>
#include <math.h>

#define BB 256     // batch
#define HH 512     // hidden
#define VV 100     // vocab
#define TT 200     // steps

// fp32 hidden-state history (proj + epilogue need fp32 h)
__device__ float g_hist[(size_t)TT * BB * HH];
// bf16 hi/lo ping-pong of previous hidden state
__device__ __nv_bfloat16 g_hh[2][BB * HH];
__device__ __nv_bfloat16 g_hl[2][BB * HH];
// packed weights: row n = jb*96 + g*16 + j  (jb=0..31, g=0..5, j=0..15), k=0..511
__device__ __nv_bfloat16 g_wh[6 * HH * HH];
__device__ __nv_bfloat16 g_wl[6 * HH * HH];
// per-batch-group step barrier counters
__device__ unsigned int g_ctrs[4];

__device__ __forceinline__ float sigmoidf_(float x) {
    return 1.0f / (1.0f + expf(-x));
}

// ---------------------------------------------------------------------------
// async / mma / sync helpers
// ---------------------------------------------------------------------------
__device__ __forceinline__ void cp_async16(void* smem_dst, const void* gmem_src) {
    unsigned int s = (unsigned int)__cvta_generic_to_shared(smem_dst);
    asm volatile("cp.async.cg.shared.global [%0], [%1], 16;\n" :: "r"(s), "l"(gmem_src));
}
#define CP_COMMIT() asm volatile("cp.async.commit_group;\n" ::: "memory")
#define CP_WAIT(n)  asm volatile("cp.async.wait_group %0;\n" :: "n"(n) : "memory")

__device__ __forceinline__ void ldsm4(uint32_t r[4], const void* p) {
    unsigned int s = (unsigned int)__cvta_generic_to_shared(p);
    asm volatile("ldmatrix.sync.aligned.m8n8.x4.shared.b16 {%0,%1,%2,%3}, [%4];"
                 : "=r"(r[0]), "=r"(r[1]), "=r"(r[2]), "=r"(r[3]) : "r"(s));
}

__device__ __forceinline__ void mma_bf16(float d[4], const uint32_t a[4],
                                         uint32_t b0, uint32_t b1) {
    asm volatile(
        "mma.sync.aligned.m16n8k16.row.col.f32.bf16.bf16.f32 "
        "{%0,%1,%2,%3}, {%4,%5,%6,%7}, {%8,%9}, {%0,%1,%2,%3};"
        : "+f"(d[0]), "+f"(d[1]), "+f"(d[2]), "+f"(d[3])
        : "r"(a[0]), "r"(a[1]), "r"(a[2]), "r"(a[3]), "r"(b0), "r"(b1));
}

__device__ __forceinline__ unsigned int ld_acq(const unsigned int* p) {
    unsigned int v;
    asm volatile("ld.acquire.gpu.u32 %0, [%1];" : "=r"(v) : "l"(p));
    return v;
}

// ---------------------------------------------------------------------------
// One-time weight prep: pack + split fp32 -> bf16 hi/lo.
// ---------------------------------------------------------------------------
__global__ __launch_bounds__(256) void prep_weights(
    const float* __restrict__ w_ih, const float* __restrict__ w_hh)
{
    int idx = blockIdx.x * 256 + threadIdx.x;
    if (idx >= 6 * HH * HH) return;
    int n = idx / HH, k = idx % HH;
    int jb = n / 96, rr = n % 96, g = rr / 16, j = rr % 16;
    const float* src = (g < 3) ? w_ih : w_hh;
    float v = src[(size_t)((g % 3) * HH + jb * 16 + j) * HH + k];
    __nv_bfloat16 hi = __float2bfloat16(v);
    g_wh[idx] = hi;
    g_wl[idx] = __float2bfloat16(v - __bfloat162float(hi));
}

__global__ void reset_ctr_kernel() {
    if (threadIdx.x < 4) g_ctrs[threadIdx.x] = 0u;
}

// ---------------------------------------------------------------------------
// Convert fp32 h -> bf16 hi/lo (after step 0)
// ---------------------------------------------------------------------------
__global__ __launch_bounds__(256) void convert_h(
    const float* __restrict__ h, __nv_bfloat16* __restrict__ hh,
    __nv_bfloat16* __restrict__ hl)
{
    int idx = blockIdx.x * 256 + threadIdx.x;
    if (idx >= BB * HH) return;
    float v = h[idx];
    __nv_bfloat16 hi = __float2bfloat16(v);
    hh[idx] = hi;
    hl[idx] = __float2bfloat16(v - __bfloat162float(hi));
}

// ---------------------------------------------------------------------------
// Persistent tensor-core GRU, v6: R7 skeleton, 6 warps with 32x32 warp tiles.
// B fragments reused across 2 m16 tiles per warp -> LDSM traffic -33%.
// Grid (32 jb, 4 bq) = 128 blocks, 192 threads (6 warps: 2 mw x 3 nv(n=32)).
// B tile (96x512, hi+lo) XOR-swizzled, SMEM-resident whole kernel.
// A (h hi/lo) streamed per step, k=64 chunks, double buffer.
// Step barrier: per-bq-group atomic counter (fan-in 32). Exactly R7's loop.
// ---------------------------------------------------------------------------
#define THR    192
#define B_MATS (96 * 512)                   // bf16 per B matrix (swizzled, no pad)
#define OFF_A  (2 * B_MATS)                 // 98304 bf16
#define A_MATS (64 * 64)                    // bf16 per A matrix per chunk (k=64)
#define A_BUF  (2 * A_MATS)                 // hi+lo per buffer = 8192 bf16
#define SMEM_P ((OFF_A + 2 * A_BUF) * 2)    // 229376 bytes (224 KB)
#define NCH    8                            // K chunks of 64

__global__ __launch_bounds__(THR) void gru_persistent(
    const float* __restrict__ b_ih,
    const float* __restrict__ b_hh,
    float* __restrict__ hist,                 // [TT][BB][HH]
    __nv_bfloat16* __restrict__ hh_base,      // [2][BB*HH]
    __nv_bfloat16* __restrict__ hl_base)
{
    extern __shared__ __align__(16) __nv_bfloat16 dsm[];

    const int tid  = threadIdx.x;
    const int lane = tid & 31;
    const int w    = tid >> 5;           // 0..5
    const int mw   = w & 1;              // m32 half (rows 32*mw..+31)
    const int nv   = w >> 1;             // 0..2, n=32 each
    const int jb   = blockIdx.x;         // 0..31
    const int bq   = blockIdx.y;         // 0..3
    const int b0   = bq * 64;

    // ================= resident B load (swizzled, once) =================
    for (int i = tid; i < 2 * 96 * 64; i += THR) {     // 16B granules
        const int mat = i / (96 * 64);
        const int rr  = i % (96 * 64);
        const int row = rr >> 6;
        const int g   = rr & 63;
        const int gs  = (g & 56) | ((g ^ row) & 7);
        const __nv_bfloat16* src =
            (mat ? g_wl : g_wh) + (size_t)(jb * 96 + row) * HH + g * 8;
        cp_async16(dsm + mat * B_MATS + row * 512 + gs * 8, src);
    }
    CP_COMMIT();

    // ========== per-thread A-chunk cp.async descriptors (<=6 each) =========
    // per chunk: 2 mats x 64 rows x 8 granules = 1024 granules
    int aMat[6], aDst[6], aSrc[6];
    #pragma unroll
    for (int k = 0; k < 6; k++) {
        const int i = tid + THR * k;
        if (i < 1024) {
            const int mat = i >> 9;
            const int r   = (i >> 3) & 63;
            const int g   = i & 7;
            aMat[k] = mat;
            aDst[k] = mat * A_MATS + r * 64 + ((g ^ (r & 7)) * 8);
            aSrc[k] = (b0 + r) * HH + g * 8;
        }
    }

    // ================= ldmatrix lane invariants =================
    int a_base[2];
    #pragma unroll
    for (int mi = 0; mi < 2; mi++)
        a_base[mi] = (mw * 32 + mi * 16 + (lane & 15)) * 64;
    const int a_r7 = lane & 7;           // (row & 7) is mi-invariant
    const int a_g0 = (lane >> 4);
    const int b_rowL = (lane & 7) + ((lane & 16) ? 8 : 0);
    const int b_g0   = (lane & 8) ? 1 : 0;
    int b_base[2], b_r7[2];
    #pragma unroll
    for (int p = 0; p < 2; p++) {
        const int brow = nv * 32 + p * 16 + b_rowL;
        b_base[p] = brow * 512;
        b_r7[p]   = brow & 7;
    }

    // ================= epilogue per-thread state =================
    // outputs e = tid + 192*n (<1024): (b = e>>4, j = e&15)
    float hp[6], br_[6], bz_[6], bni_[6], bnh_[6];
    int   ooff[6];
    #pragma unroll
    for (int n = 0; n < 6; n++) {
        const int e = tid + THR * n;
        if (e < 1024) {
            const int b  = e >> 4;
            const int j  = e & 15;
            const int jg = jb * 16 + j;
            ooff[n] = (b0 + b) * HH + jg;
            br_[n]  = b_ih[jg] + b_hh[jg];
            bz_[n]  = b_ih[HH + jg] + b_hh[HH + jg];
            bni_[n] = b_ih[2 * HH + jg];
            bnh_[n] = b_hh[2 * HH + jg];
            hp[n]   = hist[ooff[n]];
        }
    }

    CP_WAIT(0);
    __syncthreads();

    float acc[2][4][4];
    #pragma unroll
    for (int mi = 0; mi < 2; mi++)
        #pragma unroll
        for (int f = 0; f < 4; f++)
            #pragma unroll
            for (int i = 0; i < 4; i++) acc[mi][f][i] = 0.0f;

    float* sG = (float*)(dsm + OFF_A);   // [64][100] gate exchange (aliases A)

    for (int t = 1; t < TT; t++) {
        const __nv_bfloat16* srcH = hh_base + (size_t)((t - 1) & 1) * BB * HH;
        const __nv_bfloat16* srcL = hl_base + (size_t)((t - 1) & 1) * BB * HH;

        // prologue: chunk 0 -> buf 0
        {
            __nv_bfloat16* buf = dsm + OFF_A;
            #pragma unroll
            for (int k = 0; k < 6; k++)
                if (tid + THR * k < 1024)
                    cp_async16(buf + aDst[k], (aMat[k] ? srcL : srcH) + aSrc[k]);
            CP_COMMIT();
        }

        #pragma unroll 1
        for (int c = 0; c < NCH; c++) {
            if (c + 1 < NCH) {
                __nv_bfloat16* buf = dsm + OFF_A + ((c + 1) & 1) * A_BUF;
                const int k0 = (c + 1) * 64;
                #pragma unroll
                for (int k = 0; k < 6; k++)
                    if (tid + THR * k < 1024)
                        cp_async16(buf + aDst[k],
                                   (aMat[k] ? srcL : srcH) + aSrc[k] + k0);
                CP_COMMIT();
                CP_WAIT(1);
            } else {
                CP_WAIT(0);
            }
            __syncthreads();

            const __nv_bfloat16* bufA = dsm + OFF_A + (c & 1) * A_BUF;
            #pragma unroll
            for (int q = 0; q < 4; q++) {
                uint32_t aH[2][4], aL[2][4];
                const int gsA = ((2 * q + a_g0) ^ a_r7) * 8;
                #pragma unroll
                for (int mi = 0; mi < 2; mi++) {
                    ldsm4(aH[mi], bufA + a_base[mi] + gsA);
                    ldsm4(aL[mi], bufA + A_MATS + a_base[mi] + gsA);
                }
                const int gqB = c * 8 + 2 * q + b_g0;
                #pragma unroll
                for (int p = 0; p < 2; p++) {
                    const int gsB = (gqB & 56) | ((gqB ^ b_r7[p]) & 7);
                    const int off = b_base[p] + gsB * 8;
                    uint32_t bh[4], bl[4];
                    ldsm4(bh, dsm + off);
                    ldsm4(bl, dsm + B_MATS + off);
                    #pragma unroll
                    for (int mi = 0; mi < 2; mi++) {
                        mma_bf16(acc[mi][2 * p],     aH[mi], bh[0], bh[1]);
                        mma_bf16(acc[mi][2 * p + 1], aH[mi], bh[2], bh[3]);
                        mma_bf16(acc[mi][2 * p],     aH[mi], bl[0], bl[1]);
                        mma_bf16(acc[mi][2 * p + 1], aH[mi], bl[2], bl[3]);
                        mma_bf16(acc[mi][2 * p],     aL[mi], bh[0], bh[1]);
                        mma_bf16(acc[mi][2 * p + 1], aL[mi], bh[2], bh[3]);
                    }
                }
            }
            __syncthreads();   // buffer consumed (and pre-sG for last chunk)
        }

        // ---- write fragments to sG[64][100] ----
        #pragma unroll
        for (int mi = 0; mi < 2; mi++) {
            const int rb = mw * 32 + mi * 16 + (lane >> 2);
            #pragma unroll
            for (int f = 0; f < 4; f++) {
                const int cb = nv * 32 + f * 8 + (lane & 3) * 2;
                sG[rb * 100 + cb]           = acc[mi][f][0];
                sG[rb * 100 + cb + 1]       = acc[mi][f][1];
                sG[(rb + 8) * 100 + cb]     = acc[mi][f][2];
                sG[(rb + 8) * 100 + cb + 1] = acc[mi][f][3];
            }
        }
        __syncthreads();

        // ---- gate epilogue ----
        {
            __nv_bfloat16* dstH = hh_base + (size_t)(t & 1) * BB * HH;
            __nv_bfloat16* dstL = hl_base + (size_t)(t & 1) * BB * HH;
            float* hout = hist + (size_t)t * BB * HH;
            #pragma unroll
            for (int n = 0; n < 6; n++) {
                const int e = tid + THR * n;
                if (e < 1024) {
                    const int b = e >> 4, j = e & 15;
                    const float gr = sG[b * 100 + j];
                    const float gz = sG[b * 100 + 16 + j];
                    const float gn = sG[b * 100 + 32 + j];
                    const float hr = sG[b * 100 + 48 + j];
                    const float hz = sG[b * 100 + 64 + j];
                    const float hn = sG[b * 100 + 80 + j];
                    const float rv = sigmoidf_(gr + hr + br_[n]);
                    const float zv = sigmoidf_(gz + hz + bz_[n]);
                    const float nn = tanhf(gn + bni_[n] + rv * (hn + bnh_[n]));
                    const float hv = (1.0f - zv) * nn + zv * hp[n];
                    hp[n] = hv;
                    hout[ooff[n]] = hv;
                    const __nv_bfloat16 hi = __float2bfloat16(hv);
                    dstH[ooff[n]] = hi;
                    dstL[ooff[n]] = __float2bfloat16(hv - __bfloat162float(hi));
                }
            }
        }
        __threadfence();

        // reset accumulators
        #pragma unroll
        for (int mi = 0; mi < 2; mi++)
            #pragma unroll
            for (int f = 0; f < 4; f++)
                #pragma unroll
                for (int i = 0; i < 4; i++) acc[mi][f][i] = 0.0f;

        __syncthreads();   // epilogue stores + sG reads done

        // ---- per-group grid barrier (R7 form; skip after final step) ----
        if (t < TT - 1) {
            if (tid == 0) {
                atomicAdd(&g_ctrs[bq], 1u);
                const unsigned int target = (unsigned int)t * 32u;
                unsigned int v;
                do {
                    v = ld_acq(&g_ctrs[bq]);
                } while (v < target);
            }
            __syncthreads();
        }
    }
}

// ---------------------------------------------------------------------------
// Generic fp32 GRU step — used only for t = 0 (x = embed row, h = feat).
// ---------------------------------------------------------------------------
__global__ __launch_bounds__(256) void gru_step_kernel(
    const float* __restrict__ x, int xs,
    const float* __restrict__ h,
    const float* __restrict__ w_ih,
    const float* __restrict__ w_hh,
    const float* __restrict__ b_ih,
    const float* __restrict__ b_hh,
    float* __restrict__ h_out)
{
    __shared__ float sX[32][32];
    __shared__ float sH[32][32];
    __shared__ float sWih[3][32][32];
    __shared__ float sWhh[3][32][32];

    const int tid = threadIdx.x;
    const int tj  = tid & 31;
    const int tb  = tid >> 5;
    const int j0  = blockIdx.x * 32;
    const int b0  = blockIdx.y * 32;

    float acc[4][6];
    #pragma unroll
    for (int i = 0; i < 4; i++)
        #pragma unroll
        for (int g = 0; g < 6; g++) acc[i][g] = 0.0f;

    const int lb  = tid >> 3;
    const int lk4 = (tid & 7) * 4;

    for (int k0 = 0; k0 < HH; k0 += 32) {
        float4 xv4 = *(const float4*)(x + (size_t)(b0 + lb) * (size_t)xs + k0 + lk4);
        *(float4*)&sX[lb][lk4] = xv4;
        float4 hv4 = *(const float4*)(h + (size_t)(b0 + lb) * HH + k0 + lk4);
        *(float4*)&sH[lb][lk4] = hv4;
        #pragma unroll
        for (int g = 0; g < 3; g++) {
            float4 wi = *(const float4*)(w_ih + (size_t)(g * HH + j0 + lb) * HH + k0 + lk4);
            sWih[g][lk4 + 0][lb] = wi.x;
            sWih[g][lk4 + 1][lb] = wi.y;
            sWih[g][lk4 + 2][lb] = wi.z;
            sWih[g][lk4 + 3][lb] = wi.w;
            float4 wh = *(const float4*)(w_hh + (size_t)(g * HH + j0 + lb) * HH + k0 + lk4);
            sWhh[g][lk4 + 0][lb] = wh.x;
            sWhh[g][lk4 + 1][lb] = wh.y;
            sWhh[g][lk4 + 2][lb] = wh.z;
            sWhh[g][lk4 + 3][lb] = wh.w;
        }
        __syncthreads();

        #pragma unroll
        for (int kk = 0; kk < 32; kk++) {
            const float wi0 = sWih[0][kk][tj];
            const float wi1 = sWih[1][kk][tj];
            const float wi2 = sWih[2][kk][tj];
            const float wh0 = sWhh[0][kk][tj];
            const float wh1 = sWhh[1][kk][tj];
            const float wh2 = sWhh[2][kk][tj];
            #pragma unroll
            for (int i = 0; i < 4; i++) {
                const float xv = sX[tb * 4 + i][kk];
                const float hv = sH[tb * 4 + i][kk];
                acc[i][0] += xv * wi0;
                acc[i][1] += xv * wi1;
                acc[i][2] += xv * wi2;
                acc[i][3] += hv * wh0;
                acc[i][4] += hv * wh1;
                acc[i][5] += hv * wh2;
            }
        }
        __syncthreads();
    }

    const int j = j0 + tj;
    const float bir  = b_ih[j],          bhr = b_hh[j];
    const float biz  = b_ih[HH + j],     bhz = b_hh[HH + j];
    const float bin_ = b_ih[2 * HH + j], bhn = b_hh[2 * HH + j];
    #pragma unroll
    for (int i = 0; i < 4; i++) {
        const int b = b0 + tb * 4 + i;
        const float r = sigmoidf_(acc[i][0] + bir + acc[i][3] + bhr);
        const float z = sigmoidf_(acc[i][1] + biz + acc[i][4] + bhz);
        const float n = tanhf(acc[i][2] + bin_ + r * (acc[i][5] + bhn));
        const float hp = h[(size_t)b * HH + j];
        h_out[(size_t)b * HH + j] = (1.0f - z) * n + z * hp;
    }
}

// ---------------------------------------------------------------------------
// Projection: out[b][v][t] = hist[t][b][:] . proj_w[v][:] + proj_b[v]
// ---------------------------------------------------------------------------
__global__ __launch_bounds__(512) void proj_kernel(
    const float* __restrict__ proj_w,
    const float* __restrict__ proj_b,
    float* __restrict__ out)
{
    __shared__ float sH[TT][33];
    __shared__ float sW[VV][33];

    const int b   = blockIdx.x;
    const int tid = threadIdx.x;
    const int tg  = tid % 25;
    const int vg  = tid / 25;
    const bool active = (tid < 500);

    float acc[8][5];
    #pragma unroll
    for (int i = 0; i < 8; i++)
        #pragma unroll
        for (int jv = 0; jv < 5; jv++) acc[i][jv] = 0.0f;

    for (int k0 = 0; k0 < HH; k0 += 32) {
        for (int idx = tid; idx < TT * 32; idx += 512) {
            const int t = idx >> 5, k = idx & 31;
            sH[t][k] = g_hist[((size_t)t * BB + b) * HH + k0 + k];
        }
        for (int idx = tid; idx < VV * 32; idx += 512) {
            const int v = idx >> 5, k = idx & 31;
            sW[v][k] = proj_w[(size_t)v * HH + k0 + k];
        }
        __syncthreads();

        if (active) {
            #pragma unroll
            for (int kk = 0; kk < 32; kk++) {
                float wv[5];
                #pragma unroll
                for (int jv = 0; jv < 5; jv++) wv[jv] = sW[vg * 5 + jv][kk];
                #pragma unroll
                for (int i = 0; i < 8; i++) {
                    const float hv = sH[tg + 25 * i][kk];
                    #pragma unroll
                    for (int jv = 0; jv < 5; jv++) acc[i][jv] += hv * wv[jv];
                }
            }
        }
        __syncthreads();
    }

    if (active) {
        float pb[5];
        #pragma unroll
        for (int jv = 0; jv < 5; jv++) pb[jv] = proj_b[vg * 5 + jv];
        #pragma unroll
        for (int i = 0; i < 8; i++) {
            const int t = tg + 25 * i;
            #pragma unroll
            for (int jv = 0; jv < 5; jv++) {
                const int v = vg * 5 + jv;
                out[((size_t)b * VV + v) * TT + t] = acc[i][jv] + pb[jv];
            }
        }
    }
}

// ---------------------------------------------------------------------------
extern "C" void kernel_launch(void* const* d_in, const int* in_sizes, int n_in,
                              void* d_out, int out_size)
{
    (void)in_sizes; (void)n_in; (void)out_size;
    const float* feat   = (const float*)d_in[0];
    const float* embed  = (const float*)d_in[1];
    const float* w_ih   = (const float*)d_in[2];
    const float* w_hh   = (const float*)d_in[3];
    const float* b_ih   = (const float*)d_in[4];
    const float* b_hh   = (const float*)d_in[5];
    const float* proj_w = (const float*)d_in[6];
    const float* proj_b = (const float*)d_in[7];
    float* out = (float*)d_out;

    float* hist = nullptr;
    cudaGetSymbolAddress((void**)&hist, g_hist);
    __nv_bfloat16* hhp = nullptr;
    cudaGetSymbolAddress((void**)&hhp, g_hh);
    __nv_bfloat16* hlp = nullptr;
    cudaGetSymbolAddress((void**)&hlp, g_hl);

    cudaFuncSetAttribute(gru_persistent,
                         cudaFuncAttributeMaxDynamicSharedMemorySize, SMEM_P);

    prep_weights<<<(6 * HH * HH + 255) / 256, 256>>>(w_ih, w_hh);
    reset_ctr_kernel<<<1, 32>>>();

    // step 0: x = embed[SOS=0] broadcast, h = feat  -> hist[0]
    gru_step_kernel<<<dim3(HH / 32, BB / 32), 256>>>(embed, 0, feat,
                                                     w_ih, w_hh, b_ih, b_hh, hist);
    convert_h<<<(BB * HH + 255) / 256, 256>>>(hist, hhp, hlp);   // -> pp slot 0

    // steps 1..199: persistent tensor-core kernel (one wave of 128 blocks)
    gru_persistent<<<dim3(32, 4), THR, SMEM_P>>>(b_ih, b_hh, hist, hhp, hlp);

    proj_kernel<<<BB, 512>>>(proj_w, proj_b, out);
}

// round 14
// speedup vs baseline: 1.1911x; 1.0308x over previous
#include <cuda_runtime.h>
#include <cuda_bf16.h>
#include <stdint.h>
#include <math.h>

#define BB 256     // batch
#define HH 512     // hidden
#define VV 100     // vocab
#define TT 200     // steps

// fp32 hidden-state history (proj + epilogue need fp32 h)
__device__ float g_hist[(size_t)TT * BB * HH];
// bf16 hi/lo ping-pong of previous hidden state
__device__ __nv_bfloat16 g_hh[2][BB * HH];
__device__ __nv_bfloat16 g_hl[2][BB * HH];
// packed weights: row n = jb*96 + g*16 + j  (jb=0..31, g=0..5, j=0..15), k=0..511
__device__ __nv_bfloat16 g_wh[6 * HH * HH];
__device__ __nv_bfloat16 g_wl[6 * HH * HH];
// per-batch-group step barrier counters
__device__ unsigned int g_ctrs[4];

__device__ __forceinline__ float sigmoidf_(float x) {
    return 1.0f / (1.0f + expf(-x));
}

// ---------------------------------------------------------------------------
// async / mma / sync helpers
// ---------------------------------------------------------------------------
__device__ __forceinline__ void cp_async16(void* smem_dst, const void* gmem_src) {
    unsigned int s = (unsigned int)__cvta_generic_to_shared(smem_dst);
    asm volatile("cp.async.cg.shared.global [%0], [%1], 16;\n" :: "r"(s), "l"(gmem_src));
}
#define CP_COMMIT() asm volatile("cp.async.commit_group;\n" ::: "memory")
#define CP_WAIT(n)  asm volatile("cp.async.wait_group %0;\n" :: "n"(n) : "memory")

__device__ __forceinline__ void ldsm4(uint32_t r[4], const void* p) {
    unsigned int s = (unsigned int)__cvta_generic_to_shared(p);
    asm volatile("ldmatrix.sync.aligned.m8n8.x4.shared.b16 {%0,%1,%2,%3}, [%4];"
                 : "=r"(r[0]), "=r"(r[1]), "=r"(r[2]), "=r"(r[3]) : "r"(s));
}

__device__ __forceinline__ void mma_bf16(float d[4], const uint32_t a[4],
                                         uint32_t b0, uint32_t b1) {
    asm volatile(
        "mma.sync.aligned.m16n8k16.row.col.f32.bf16.bf16.f32 "
        "{%0,%1,%2,%3}, {%4,%5,%6,%7}, {%8,%9}, {%0,%1,%2,%3};"
        : "+f"(d[0]), "+f"(d[1]), "+f"(d[2]), "+f"(d[3])
        : "r"(a[0]), "r"(a[1]), "r"(a[2]), "r"(a[3]), "r"(b0), "r"(b1));
}

__device__ __forceinline__ unsigned int ld_acq(const unsigned int* p) {
    unsigned int v;
    asm volatile("ld.acquire.gpu.u32 %0, [%1];" : "=r"(v) : "l"(p));
    return v;
}

__device__ __forceinline__ void mbar_wait(uint32_t addr, uint32_t parity) {
    asm volatile(
        "{\n\t.reg .pred P;\n"
        "WL_%=:\n\t"
        "mbarrier.try_wait.parity.acquire.cta.shared::cta.b64 P, [%0], %1, 0x989680;\n\t"
        "@!P bra WL_%=;\n\t}"
        :: "r"(addr), "r"(parity) : "memory");
}
__device__ __forceinline__ void mbar_arrive(uint32_t addr) {
    asm volatile("mbarrier.arrive.shared.b64 _, [%0];" :: "r"(addr) : "memory");
}

// ---------------------------------------------------------------------------
// One-time weight prep: pack + split fp32 -> bf16 hi/lo.
// ---------------------------------------------------------------------------
__global__ __launch_bounds__(256) void prep_weights(
    const float* __restrict__ w_ih, const float* __restrict__ w_hh)
{
    int idx = blockIdx.x * 256 + threadIdx.x;
    if (idx >= 6 * HH * HH) return;
    int n = idx / HH, k = idx % HH;
    int jb = n / 96, rr = n % 96, g = rr / 16, j = rr % 16;
    const float* src = (g < 3) ? w_ih : w_hh;
    float v = src[(size_t)((g % 3) * HH + jb * 16 + j) * HH + k];
    __nv_bfloat16 hi = __float2bfloat16(v);
    g_wh[idx] = hi;
    g_wl[idx] = __float2bfloat16(v - __bfloat162float(hi));
}

__global__ void reset_ctr_kernel() {
    if (threadIdx.x < 4) g_ctrs[threadIdx.x] = 0u;
}

// ---------------------------------------------------------------------------
// Convert fp32 h -> bf16 hi/lo (after step 0)
// ---------------------------------------------------------------------------
__global__ __launch_bounds__(256) void convert_h(
    const float* __restrict__ h, __nv_bfloat16* __restrict__ hh,
    __nv_bfloat16* __restrict__ hl)
{
    int idx = blockIdx.x * 256 + threadIdx.x;
    if (idx >= BB * HH) return;
    float v = h[idx];
    __nv_bfloat16 hi = __float2bfloat16(v);
    hh[idx] = hi;
    hl[idx] = __float2bfloat16(v - __bfloat162float(hi));
}

// ---------------------------------------------------------------------------
// Persistent tensor-core GRU, v7: warp-specialized producer/consumer.
// Grid (32 jb, 4 bq) = 128 blocks, 416 threads (13 warps).
// Warps 0-11: consumers, R7 tiling (4 mw x 3 nv, n=32 each).
// Warp 12:   sole A-producer (cp.async + mbarrier full signal, noinc).
// B tile (96x512, hi+lo) XOR-swizzled, SMEM-resident.
// A streamed per step, k=64 chunks, 2-buffer ring, full/empty mbarriers.
// NO block-wide bar.sync in the chunk loop.
// ---------------------------------------------------------------------------
#define THR    416
#define B_MATS (96 * 512)                   // bf16 per B matrix
#define OFF_A  (2 * B_MATS)                 // 98304 bf16
#define A_MATS (64 * 64)                    // bf16 per A matrix per chunk
#define A_BUF  (2 * A_MATS)                 // hi+lo per buffer = 8192 bf16
#define MB_OFF ((OFF_A + 2 * A_BUF) * 2)    // 229376 bytes
#define SMEM_P (MB_OFF + 64)                // + mbarriers
#define NCH    8

#define BARC() asm volatile("bar.sync 1, 384;" ::: "memory")

__global__ __launch_bounds__(THR) void gru_persistent(
    const float* __restrict__ b_ih,
    const float* __restrict__ b_hh,
    float* __restrict__ hist,
    __nv_bfloat16* __restrict__ hh_base,
    __nv_bfloat16* __restrict__ hl_base)
{
    extern __shared__ __align__(16) __nv_bfloat16 dsm[];
    const uint32_t su = (uint32_t)__cvta_generic_to_shared(dsm);
    const uint32_t mb_full  = su + MB_OFF;        // full0, full1
    const uint32_t mb_empty = su + MB_OFF + 16;   // empty0, empty1

    const int tid  = threadIdx.x;
    const int lane = tid & 31;
    const int w    = tid >> 5;           // 0..12
    const int jb   = blockIdx.x;         // 0..31
    const int bq   = blockIdx.y;         // 0..3
    const int b0   = bq * 64;

    // ---- mbarrier init ----
    if (tid == 0) {
        asm volatile("mbarrier.init.shared.b64 [%0], %1;" :: "r"(mb_full),      "r"(32u) : "memory");
        asm volatile("mbarrier.init.shared.b64 [%0], %1;" :: "r"(mb_full + 8),  "r"(32u) : "memory");
        asm volatile("mbarrier.init.shared.b64 [%0], %1;" :: "r"(mb_empty),     "r"(12u) : "memory");
        asm volatile("mbarrier.init.shared.b64 [%0], %1;" :: "r"(mb_empty + 8), "r"(12u) : "memory");
    }

    // ---- resident B load (all threads) ----
    for (int i = tid; i < 2 * 96 * 64; i += THR) {
        const int mat = i / (96 * 64);
        const int rr  = i % (96 * 64);
        const int row = rr >> 6;
        const int g   = rr & 63;
        const int gs  = (g & 56) | ((g ^ row) & 7);
        const __nv_bfloat16* src =
            (mat ? g_wl : g_wh) + (size_t)(jb * 96 + row) * HH + g * 8;
        cp_async16(dsm + mat * B_MATS + row * 512 + gs * 8, src);
    }
    CP_COMMIT();
    CP_WAIT(0);
    __syncthreads();      // B visible + mbarriers initialized

    if (w == 12) {
        // =================== PRODUCER warp ===================
        int pe0 = 1, pe1 = 1;
        for (int t = 1; t < TT; t++) {
            const __nv_bfloat16* srcH = hh_base + (size_t)((t - 1) & 1) * BB * HH;
            const __nv_bfloat16* srcL = hl_base + (size_t)((t - 1) & 1) * BB * HH;
            // wait until all blocks of this group published step t-1
            if (t >= 2) {
                if (lane == 0) {
                    const unsigned int target = (unsigned int)(t - 1) * 32u;
                    while (ld_acq(&g_ctrs[bq]) < target) {}
                }
                __syncwarp();
            }
            for (int c = 0; c < NCH; c++) {
                const int b = c & 1;
                if (b == 0) { mbar_wait(mb_empty,     (uint32_t)pe0); pe0 ^= 1; }
                else        { mbar_wait(mb_empty + 8, (uint32_t)pe1); pe1 ^= 1; }
                const int k0 = c * 64;
                __nv_bfloat16* buf = dsm + OFF_A + b * A_BUF;
                #pragma unroll
                for (int n = 0; n < 32; n++) {
                    const int idx = lane + 32 * n;      // 0..1023
                    const int mat = idx >> 9;
                    const int r   = (idx >> 3) & 63;
                    const int g   = idx & 7;
                    const int dst = mat * A_MATS + r * 64 + ((g ^ (r & 7)) * 8);
                    cp_async16(buf + dst,
                               (mat ? srcL : srcH) + (b0 + r) * HH + g * 8 + k0);
                }
                asm volatile(
                    "cp.async.mbarrier.arrive.noinc.shared::cta.b64 [%0];"
                    :: "r"(mb_full + b * 8) : "memory");
            }
        }
    } else {
        // =================== CONSUMER warps (0..11) ===================
        const int mw = w & 3;
        const int nv = w >> 2;

        const int a_row  = mw * 16 + (lane & 15);
        const int a_g0   = (lane >> 4);
        const int a_base = a_row * 64;
        const int a_r7   = a_row & 7;
        const int b_rowL = (lane & 7) + ((lane & 16) ? 8 : 0);
        const int b_g0   = (lane & 8) ? 1 : 0;
        int b_base[2], b_r7[2];
        #pragma unroll
        for (int p = 0; p < 2; p++) {
            const int brow = nv * 32 + p * 16 + b_rowL;
            b_base[p] = brow * 512;
            b_r7[p]   = brow & 7;
        }
        const int r_base = mw * 16 + (lane >> 2);

        // epilogue per-thread state: e = tid + 384*n < 1024
        float hp[3], br_[3], bz_[3], bni_[3], bnh_[3];
        int   ooff[3];
        #pragma unroll
        for (int n = 0; n < 3; n++) {
            const int e = tid + 384 * n;
            if (e < 1024) {
                const int b  = e >> 4;
                const int j  = e & 15;
                const int jg = jb * 16 + j;
                ooff[n] = (b0 + b) * HH + jg;
                br_[n]  = b_ih[jg] + b_hh[jg];
                bz_[n]  = b_ih[HH + jg] + b_hh[HH + jg];
                bni_[n] = b_ih[2 * HH + jg];
                bnh_[n] = b_hh[2 * HH + jg];
                hp[n]   = hist[ooff[n]];
            }
        }

        float acc[4][4];
        #pragma unroll
        for (int f = 0; f < 4; f++)
            #pragma unroll
            for (int i = 0; i < 4; i++) acc[f][i] = 0.0f;

        float* sG = (float*)(dsm + OFF_A);   // [64][100], aliases A ring
        int pf0 = 0, pf1 = 0;

        for (int t = 1; t < TT; t++) {
            #pragma unroll 1
            for (int c = 0; c < NCH; c++) {
                const int b = c & 1;
                if (b == 0) { mbar_wait(mb_full,     (uint32_t)pf0); pf0 ^= 1; }
                else        { mbar_wait(mb_full + 8, (uint32_t)pf1); pf1 ^= 1; }

                const __nv_bfloat16* bufA = dsm + OFF_A + b * A_BUF;
                #pragma unroll
                for (int q = 0; q < 4; q++) {
                    uint32_t aH[4], aL[4];
                    const int gsA = ((2 * q + a_g0) ^ a_r7) * 8;
                    ldsm4(aH, bufA + a_base + gsA);
                    ldsm4(aL, bufA + A_MATS + a_base + gsA);
                    const int gqB = c * 8 + 2 * q + b_g0;
                    #pragma unroll
                    for (int p = 0; p < 2; p++) {
                        const int gsB = (gqB & 56) | ((gqB ^ b_r7[p]) & 7);
                        const int off = b_base[p] + gsB * 8;
                        uint32_t bh[4], bl[4];
                        ldsm4(bh, dsm + off);
                        ldsm4(bl, dsm + B_MATS + off);
                        mma_bf16(acc[2 * p],     aH, bh[0], bh[1]);
                        mma_bf16(acc[2 * p],     aH, bl[0], bl[1]);
                        mma_bf16(acc[2 * p],     aL, bh[0], bh[1]);
                        mma_bf16(acc[2 * p + 1], aH, bh[2], bh[3]);
                        mma_bf16(acc[2 * p + 1], aH, bl[2], bl[3]);
                        mma_bf16(acc[2 * p + 1], aL, bh[2], bh[3]);
                    }
                }
                // this warp's reads of buffer b done -> recycle (except last 2)
                if (c < NCH - 2) {
                    __syncwarp();
                    if (lane == 0) mbar_arrive(mb_empty + b * 8);
                }
            }

            BARC();   // all consumer warps done with chunk 6/7 reads

            // ---- write fragments to sG[64][100] ----
            #pragma unroll
            for (int f = 0; f < 4; f++) {
                const int cb = nv * 32 + f * 8 + (lane & 3) * 2;
                sG[r_base * 100 + cb]           = acc[f][0];
                sG[r_base * 100 + cb + 1]       = acc[f][1];
                sG[(r_base + 8) * 100 + cb]     = acc[f][2];
                sG[(r_base + 8) * 100 + cb + 1] = acc[f][3];
            }
            BARC();

            // ---- gate epilogue ----
            {
                __nv_bfloat16* dstH = hh_base + (size_t)(t & 1) * BB * HH;
                __nv_bfloat16* dstL = hl_base + (size_t)(t & 1) * BB * HH;
                float* hout = hist + (size_t)t * BB * HH;
                #pragma unroll
                for (int n = 0; n < 3; n++) {
                    const int e = tid + 384 * n;
                    if (e < 1024) {
                        const int b = e >> 4, j = e & 15;
                        const float gr = sG[b * 100 + j];
                        const float gz = sG[b * 100 + 16 + j];
                        const float gn = sG[b * 100 + 32 + j];
                        const float hr = sG[b * 100 + 48 + j];
                        const float hz = sG[b * 100 + 64 + j];
                        const float hn = sG[b * 100 + 80 + j];
                        const float rv = sigmoidf_(gr + hr + br_[n]);
                        const float zv = sigmoidf_(gz + hz + bz_[n]);
                        const float nn = tanhf(gn + bni_[n] + rv * (hn + bnh_[n]));
                        const float hv = (1.0f - zv) * nn + zv * hp[n];
                        hp[n] = hv;
                        hout[ooff[n]] = hv;
                        const __nv_bfloat16 hi = __float2bfloat16(hv);
                        dstH[ooff[n]] = hi;
                        dstL[ooff[n]] = __float2bfloat16(hv - __bfloat162float(hi));
                    }
                }
            }
            __threadfence();

            // reset accumulators
            #pragma unroll
            for (int f = 0; f < 4; f++)
                #pragma unroll
                for (int i = 0; i < 4; i++) acc[f][i] = 0.0f;

            // this warp's sG reads done -> release both buffers to producer
            __syncwarp();
            if (lane == 0) { mbar_arrive(mb_empty); mbar_arrive(mb_empty + 8); }

            // publish step t (producer spins; consumers never do)
            if (t < TT - 1) {
                BARC();               // all stores fenced before release
                if (tid == 0) atomicAdd(&g_ctrs[bq], 1u);
            }
        }
    }
}

// ---------------------------------------------------------------------------
// Generic fp32 GRU step — used only for t = 0 (x = embed row, h = feat).
// ---------------------------------------------------------------------------
__global__ __launch_bounds__(256) void gru_step_kernel(
    const float* __restrict__ x, int xs,
    const float* __restrict__ h,
    const float* __restrict__ w_ih,
    const float* __restrict__ w_hh,
    const float* __restrict__ b_ih,
    const float* __restrict__ b_hh,
    float* __restrict__ h_out)
{
    __shared__ float sX[32][32];
    __shared__ float sH[32][32];
    __shared__ float sWih[3][32][32];
    __shared__ float sWhh[3][32][32];

    const int tid = threadIdx.x;
    const int tj  = tid & 31;
    const int tb  = tid >> 5;
    const int j0  = blockIdx.x * 32;
    const int b0  = blockIdx.y * 32;

    float acc[4][6];
    #pragma unroll
    for (int i = 0; i < 4; i++)
        #pragma unroll
        for (int g = 0; g < 6; g++) acc[i][g] = 0.0f;

    const int lb  = tid >> 3;
    const int lk4 = (tid & 7) * 4;

    for (int k0 = 0; k0 < HH; k0 += 32) {
        float4 xv4 = *(const float4*)(x + (size_t)(b0 + lb) * (size_t)xs + k0 + lk4);
        *(float4*)&sX[lb][lk4] = xv4;
        float4 hv4 = *(const float4*)(h + (size_t)(b0 + lb) * HH + k0 + lk4);
        *(float4*)&sH[lb][lk4] = hv4;
        #pragma unroll
        for (int g = 0; g < 3; g++) {
            float4 wi = *(const float4*)(w_ih + (size_t)(g * HH + j0 + lb) * HH + k0 + lk4);
            sWih[g][lk4 + 0][lb] = wi.x;
            sWih[g][lk4 + 1][lb] = wi.y;
            sWih[g][lk4 + 2][lb] = wi.z;
            sWih[g][lk4 + 3][lb] = wi.w;
            float4 wh = *(const float4*)(w_hh + (size_t)(g * HH + j0 + lb) * HH + k0 + lk4);
            sWhh[g][lk4 + 0][lb] = wh.x;
            sWhh[g][lk4 + 1][lb] = wh.y;
            sWhh[g][lk4 + 2][lb] = wh.z;
            sWhh[g][lk4 + 3][lb] = wh.w;
        }
        __syncthreads();

        #pragma unroll
        for (int kk = 0; kk < 32; kk++) {
            const float wi0 = sWih[0][kk][tj];
            const float wi1 = sWih[1][kk][tj];
            const float wi2 = sWih[2][kk][tj];
            const float wh0 = sWhh[0][kk][tj];
            const float wh1 = sWhh[1][kk][tj];
            const float wh2 = sWhh[2][kk][tj];
            #pragma unroll
            for (int i = 0; i < 4; i++) {
                const float xv = sX[tb * 4 + i][kk];
                const float hv = sH[tb * 4 + i][kk];
                acc[i][0] += xv * wi0;
                acc[i][1] += xv * wi1;
                acc[i][2] += xv * wi2;
                acc[i][3] += hv * wh0;
                acc[i][4] += hv * wh1;
                acc[i][5] += hv * wh2;
            }
        }
        __syncthreads();
    }

    const int j = j0 + tj;
    const float bir  = b_ih[j],          bhr = b_hh[j];
    const float biz  = b_ih[HH + j],     bhz = b_hh[HH + j];
    const float bin_ = b_ih[2 * HH + j], bhn = b_hh[2 * HH + j];
    #pragma unroll
    for (int i = 0; i < 4; i++) {
        const int b = b0 + tb * 4 + i;
        const float r = sigmoidf_(acc[i][0] + bir + acc[i][3] + bhr);
        const float z = sigmoidf_(acc[i][1] + biz + acc[i][4] + bhz);
        const float n = tanhf(acc[i][2] + bin_ + r * (acc[i][5] + bhn));
        const float hp = h[(size_t)b * HH + j];
        h_out[(size_t)b * HH + j] = (1.0f - z) * n + z * hp;
    }
}

// ---------------------------------------------------------------------------
// Projection: out[b][v][t] = hist[t][b][:] . proj_w[v][:] + proj_b[v]
// ---------------------------------------------------------------------------
__global__ __launch_bounds__(512) void proj_kernel(
    const float* __restrict__ proj_w,
    const float* __restrict__ proj_b,
    float* __restrict__ out)
{
    __shared__ float sH[TT][33];
    __shared__ float sW[VV][33];

    const int b   = blockIdx.x;
    const int tid = threadIdx.x;
    const int tg  = tid % 25;
    const int vg  = tid / 25;
    const bool active = (tid < 500);

    float acc[8][5];
    #pragma unroll
    for (int i = 0; i < 8; i++)
        #pragma unroll
        for (int jv = 0; jv < 5; jv++) acc[i][jv] = 0.0f;

    for (int k0 = 0; k0 < HH; k0 += 32) {
        for (int idx = tid; idx < TT * 32; idx += 512) {
            const int t = idx >> 5, k = idx & 31;
            sH[t][k] = g_hist[((size_t)t * BB + b) * HH + k0 + k];
        }
        for (int idx = tid; idx < VV * 32; idx += 512) {
            const int v = idx >> 5, k = idx & 31;
            sW[v][k] = proj_w[(size_t)v * HH + k0 + k];
        }
        __syncthreads();

        if (active) {
            #pragma unroll
            for (int kk = 0; kk < 32; kk++) {
                float wv[5];
                #pragma unroll
                for (int jv = 0; jv < 5; jv++) wv[jv] = sW[vg * 5 + jv][kk];
                #pragma unroll
                for (int i = 0; i < 8; i++) {
                    const float hv = sH[tg + 25 * i][kk];
                    #pragma unroll
                    for (int jv = 0; jv < 5; jv++) acc[i][jv] += hv * wv[jv];
                }
            }
        }
        __syncthreads();
    }

    if (active) {
        float pb[5];
        #pragma unroll
        for (int jv = 0; jv < 5; jv++) pb[jv] = proj_b[vg * 5 + jv];
        #pragma unroll
        for (int i = 0; i < 8; i++) {
            const int t = tg + 25 * i;
            #pragma unroll
            for (int jv = 0; jv < 5; jv++) {
                const int v = vg * 5 + jv;
                out[((size_t)b * VV + v) * TT + t] = acc[i][jv] + pb[jv];
            }
        }
    }
}

// ---------------------------------------------------------------------------
extern "C" void kernel_launch(void* const* d_in, const int* in_sizes, int n_in,
                              void* d_out, int out_size)
{
    (void)in_sizes; (void)n_in; (void)out_size;
    const float* feat   = (const float*)d_in[0];
    const float* embed  = (const float*)d_in[1];
    const float* w_ih   = (const float*)d_in[2];
    const float* w_hh   = (const float*)d_in[3];
    const float* b_ih   = (const float*)d_in[4];
    const float* b_hh   = (const float*)d_in[5];
    const float* proj_w = (const float*)d_in[6];
    const float* proj_b = (const float*)d_in[7];
    float* out = (float*)d_out;

    float* hist = nullptr;
    cudaGetSymbolAddress((void**)&hist, g_hist);
    __nv_bfloat16* hhp = nullptr;
    cudaGetSymbolAddress((void**)&hhp, g_hh);
    __nv_bfloat16* hlp = nullptr;
    cudaGetSymbolAddress((void**)&hlp, g_hl);

    cudaFuncSetAttribute(gru_persistent,
                         cudaFuncAttributeMaxDynamicSharedMemorySize, SMEM_P);

    prep_weights<<<(6 * HH * HH + 255) / 256, 256>>>(w_ih, w_hh);
    reset_ctr_kernel<<<1, 32>>>();

    // step 0: x = embed[SOS=0] broadcast, h = feat  -> hist[0]
    gru_step_kernel<<<dim3(HH / 32, BB / 32), 256>>>(embed, 0, feat,
                                                     w_ih, w_hh, b_ih, b_hh, hist);
    convert_h<<<(BB * HH + 255) / 256, 256>>>(hist, hhp, hlp);   // -> pp slot 0

    // steps 1..199: persistent warp-specialized kernel (one wave of 128 blocks)
    gru_persistent<<<dim3(32, 4), THR, SMEM_P>>>(b_ih, b_hh, hist, hhp, hlp);

    proj_kernel<<<BB, 512>>>(proj_w, proj_b, out);
}

// round 15
// speedup vs baseline: 1.2060x; 1.0125x over previous
#include <cuda_runtime.h>
#include <cuda_bf16.h>
#include <stdint.h>
#include <math.h>

#define BB 256     // batch
#define HH 512     // hidden
#define VV 100     // vocab
#define TT 200     // steps

// fp32 hidden-state history
__device__ float g_hist[(size_t)TT * BB * HH];
// bf16 hi/lo ping-pong of previous hidden state
__device__ __nv_bfloat16 g_hh[2][BB * HH];
__device__ __nv_bfloat16 g_hl[2][BB * HH];
// packed weights: row n = jb*48 + g*8 + j (jb 0..63, g 0..5, j 0..7), k 0..511
__device__ __nv_bfloat16 g_wh[6 * HH * HH];
__device__ __nv_bfloat16 g_wl[6 * HH * HH];
// precomputed x-side gates for step 0: gi0[j'] = embed0 . w_ih[j'] + b_ih[j']
__device__ float g_gi0[3 * HH];
// per-batch-group step barrier counters
__device__ unsigned int g_ctrs[4];

__device__ __forceinline__ float sigmoidf_(float x) {
    return 1.0f / (1.0f + expf(-x));
}

// ---------------------------------------------------------------------------
// helpers
// ---------------------------------------------------------------------------
__device__ __forceinline__ void cp_async16(void* smem_dst, const void* gmem_src) {
    unsigned int s = (unsigned int)__cvta_generic_to_shared(smem_dst);
    asm volatile("cp.async.cg.shared.global [%0], [%1], 16;\n" :: "r"(s), "l"(gmem_src));
}
#define CP_COMMIT() asm volatile("cp.async.commit_group;\n" ::: "memory")
#define CP_WAIT(n)  asm volatile("cp.async.wait_group %0;\n" :: "n"(n) : "memory")

__device__ __forceinline__ void ldsm4(uint32_t r[4], const void* p) {
    unsigned int s = (unsigned int)__cvta_generic_to_shared(p);
    asm volatile("ldmatrix.sync.aligned.m8n8.x4.shared.b16 {%0,%1,%2,%3}, [%4];"
                 : "=r"(r[0]), "=r"(r[1]), "=r"(r[2]), "=r"(r[3]) : "r"(s));
}
__device__ __forceinline__ void ldsm2(uint32_t r[2], const void* p) {
    unsigned int s = (unsigned int)__cvta_generic_to_shared(p);
    asm volatile("ldmatrix.sync.aligned.m8n8.x2.shared.b16 {%0,%1}, [%2];"
                 : "=r"(r[0]), "=r"(r[1]) : "r"(s));
}

__device__ __forceinline__ void mma_bf16(float d[4], const uint32_t a[4],
                                         uint32_t b0, uint32_t b1) {
    asm volatile(
        "mma.sync.aligned.m16n8k16.row.col.f32.bf16.bf16.f32 "
        "{%0,%1,%2,%3}, {%4,%5,%6,%7}, {%8,%9}, {%0,%1,%2,%3};"
        : "+f"(d[0]), "+f"(d[1]), "+f"(d[2]), "+f"(d[3])
        : "r"(a[0]), "r"(a[1]), "r"(a[2]), "r"(a[3]), "r"(b0), "r"(b1));
}

__device__ __forceinline__ unsigned int ld_acq(const unsigned int* p) {
    unsigned int v;
    asm volatile("ld.acquire.gpu.u32 %0, [%1];" : "=r"(v) : "l"(p));
    return v;
}

// ---------------------------------------------------------------------------
// One-time weight prep: pack row n = jb*48 + g*8 + j; split fp32 -> bf16 hi/lo
// ---------------------------------------------------------------------------
__global__ __launch_bounds__(256) void prep_weights(
    const float* __restrict__ w_ih, const float* __restrict__ w_hh)
{
    int idx = blockIdx.x * 256 + threadIdx.x;
    if (idx >= 6 * HH * HH) return;
    int n = idx / HH, k = idx % HH;
    int jb = n / 48, rr = n % 48, g = rr / 8, j = rr % 8;
    const float* src = (g < 3) ? w_ih : w_hh;
    float v = src[(size_t)((g % 3) * HH + jb * 8 + j) * HH + k];
    __nv_bfloat16 hi = __float2bfloat16(v);
    g_wh[idx] = hi;
    g_wl[idx] = __float2bfloat16(v - __bfloat162float(hi));
}

__global__ void reset_ctr_kernel() {
    if (threadIdx.x < 4) g_ctrs[threadIdx.x] = 0u;
}

// gi0[row] = embed[0,:] . w_ih[row,:] + b_ih[row]   (warp per row)
__global__ __launch_bounds__(256) void gi0_kernel(
    const float* __restrict__ embed, const float* __restrict__ w_ih,
    const float* __restrict__ b_ih)
{
    const int row  = blockIdx.x * 8 + (threadIdx.x >> 5);
    const int lane = threadIdx.x & 31;
    if (row >= 3 * HH) return;
    float s = 0.0f;
    for (int k = lane; k < HH; k += 32)
        s += embed[k] * w_ih[(size_t)row * HH + k];
    #pragma unroll
    for (int o = 16; o; o >>= 1) s += __shfl_xor_sync(0xFFFFFFFFu, s, o);
    if (lane == 0) g_gi0[row] = s + b_ih[row];
}

// Convert fp32 vec -> bf16 hi/lo
__global__ __launch_bounds__(256) void convert_h(
    const float* __restrict__ h, __nv_bfloat16* __restrict__ hh,
    __nv_bfloat16* __restrict__ hl)
{
    int idx = blockIdx.x * 256 + threadIdx.x;
    if (idx >= BB * HH) return;
    float v = h[idx];
    __nv_bfloat16 hi = __float2bfloat16(v);
    hh[idx] = hi;
    hl[idx] = __float2bfloat16(v - __bfloat162float(hi));
}

// ---------------------------------------------------------------------------
// Persistent tensor-core GRU, v8: half-size blocks for 2 CTAs/SM co-residency.
// Grid (64 jb, 4 bq) = 256 blocks (all resident), 256 threads (8 warps:
// 4 mw x 2 nv, warp tile m16 x n24). Block tile: 64 batch x 48 n (8 j x 6 g).
// B (48x512 hi+lo, XOR-swizzled 512B rows) SMEM-resident: 96 KB.
// A streamed per step, k=32 chunks (16 chunks), double buffer, permuted
// conflict-free 64B rows. Step 0 folded in (x-gates from g_gi0).
// ---------------------------------------------------------------------------
#define THR    256
#define B_MATS (48 * 512)                   // bf16 units per B matrix
#define OFF_A  (2 * B_MATS)                 // 49152 units
#define A_MATS (64 * 32)                    // 2048 units per A matrix per chunk
#define A_BUF  (2 * A_MATS)                 // hi+lo per buffer
#define SMEM_P ((OFF_A + 2 * A_BUF) * 2)    // 114688 bytes (112 KB)
#define NCH    16

__global__ __launch_bounds__(THR, 2) void gru_persistent(
    const float* __restrict__ feat,
    const float* __restrict__ b_ih,
    const float* __restrict__ b_hh,
    float* __restrict__ hist,
    __nv_bfloat16* __restrict__ hh_base,
    __nv_bfloat16* __restrict__ hl_base)
{
    extern __shared__ __align__(16) __nv_bfloat16 dsm[];

    const int tid  = threadIdx.x;
    const int lane = tid & 31;
    const int w    = tid >> 5;           // 0..7
    const int mw   = w & 3;              // m16 tile
    const int nv   = w >> 2;             // 0..1, n=24 each
    const int jb   = blockIdx.x;         // 0..63
    const int bq   = blockIdx.y;         // 0..3
    const int b0   = bq * 64;

    // ---- resident B load (swizzled, once) ----
    for (int i = tid; i < 2 * 48 * 64; i += THR) {
        const int mat = i / (48 * 64);
        const int rr  = i % (48 * 64);
        const int row = rr >> 6;
        const int g   = rr & 63;
        const int gs  = (g & 56) | ((g ^ (row & 7)) & 7);
        const __nv_bfloat16* src =
            (mat ? g_wl : g_wh) + (size_t)(jb * 48 + row) * HH + g * 8;
        cp_async16(dsm + mat * B_MATS + row * 512 + gs * 8, src);
    }
    CP_COMMIT();

    // ---- A cp.async descriptors: 512 granules/chunk, 2 per thread ----
    int aMat[2], aDst[2], aSrc[2];
    #pragma unroll
    for (int n = 0; n < 2; n++) {
        const int idx = tid + THR * n;   // 0..511
        const int mat = idx >> 8;
        const int r   = (idx >> 2) & 63;
        const int g   = idx & 3;
        const int col = (g + ((r & 7) >> 1)) & 3;   // conflict-free 64B rows
        aMat[n] = mat;
        aDst[n] = mat * A_MATS + r * 32 + col * 8;
        aSrc[n] = (b0 + r) * HH + g * 8;
    }

    // ---- ldmatrix lane invariants ----
    const int a_row = mw * 16 + (lane & 15);
    const int a_g0  = lane >> 4;             // k-half within k16
    const int a_sh  = (a_row & 7) >> 1;      // permute shift
    const int b_g0  = (lane & 8) ? 1 : 0;
    const int brow4 = nv * 24 + (lane & 7) + ((lane & 16) ? 8 : 0);
    const int base4 = brow4 * 512;
    const int r7_4  = brow4 & 7;
    const int brow2 = nv * 24 + 16 + (lane & 7);
    const int base2 = brow2 * 512;
    const int r7_2  = brow2 & 7;
    const int g2_0  = (lane & 8) ? 1 : 0;
    const int r_base = mw * 16 + (lane >> 2);

    // ---- epilogue per-thread state: 2 outputs (e = tid, tid+256) ----
    float hp[2], br_[2], bz_[2], bni_[2], bnh_[2];
    int   ooff[2], jgv[2];
    #pragma unroll
    for (int n = 0; n < 2; n++) {
        const int e  = tid + THR * n;        // 0..511
        const int b  = e >> 3;
        const int j  = e & 7;
        const int jg = jb * 8 + j;
        jgv[n]  = jg;
        ooff[n] = (b0 + b) * HH + jg;
        br_[n]  = b_ih[jg] + b_hh[jg];
        bz_[n]  = b_ih[HH + jg] + b_hh[HH + jg];
        bni_[n] = b_ih[2 * HH + jg];
        bnh_[n] = b_hh[2 * HH + jg];
        hp[n]   = feat[ooff[n]];             // h_prev for step 0
    }

    CP_WAIT(0);
    __syncthreads();

    float acc[3][4];
    #pragma unroll
    for (int f = 0; f < 3; f++)
        #pragma unroll
        for (int i = 0; i < 4; i++) acc[f][i] = 0.0f;

    float* sG = (float*)(dsm + OFF_A);   // [64][52] gate exchange (aliases A)

    for (int t = 0; t < TT; t++) {
        const __nv_bfloat16* srcH = hh_base + (size_t)(t & 1) * BB * HH;
        const __nv_bfloat16* srcL = hl_base + (size_t)(t & 1) * BB * HH;

        // prologue: chunk 0 -> buf 0
        {
            __nv_bfloat16* buf = dsm + OFF_A;
            cp_async16(buf + aDst[0], (aMat[0] ? srcL : srcH) + aSrc[0]);
            cp_async16(buf + aDst[1], (aMat[1] ? srcL : srcH) + aSrc[1]);
            CP_COMMIT();
        }

        #pragma unroll 1
        for (int c = 0; c < NCH; c++) {
            if (c + 1 < NCH) {
                __nv_bfloat16* buf = dsm + OFF_A + ((c + 1) & 1) * A_BUF;
                const int k0 = (c + 1) * 32;
                cp_async16(buf + aDst[0], (aMat[0] ? srcL : srcH) + aSrc[0] + k0);
                cp_async16(buf + aDst[1], (aMat[1] ? srcL : srcH) + aSrc[1] + k0);
                CP_COMMIT();
                CP_WAIT(1);
            } else {
                CP_WAIT(0);
            }
            __syncthreads();

            const __nv_bfloat16* bufA = dsm + OFF_A + (c & 1) * A_BUF;
            #pragma unroll
            for (int q = 0; q < 2; q++) {
                uint32_t aH[4], aL[4], bh4[4], bl4[4], bh2[2], bl2[2];
                const int gg   = 2 * q + a_g0;
                const int aoff = a_row * 32 + (((gg + a_sh) & 3) << 3);
                ldsm4(aH, bufA + aoff);
                ldsm4(aL, bufA + A_MATS + aoff);
                const int gq4 = c * 4 + 2 * q + b_g0;
                const int gs4 = (gq4 & 56) | ((gq4 ^ r7_4) & 7);
                ldsm4(bh4, dsm + base4 + gs4 * 8);
                ldsm4(bl4, dsm + B_MATS + base4 + gs4 * 8);
                const int gq2 = c * 4 + 2 * q + g2_0;
                const int gs2 = (gq2 & 56) | ((gq2 ^ r7_2) & 7);
                ldsm2(bh2, dsm + base2 + gs2 * 8);
                ldsm2(bl2, dsm + B_MATS + base2 + gs2 * 8);

                mma_bf16(acc[0], aH, bh4[0], bh4[1]);
                mma_bf16(acc[1], aH, bh4[2], bh4[3]);
                mma_bf16(acc[2], aH, bh2[0], bh2[1]);
                mma_bf16(acc[0], aH, bl4[0], bl4[1]);
                mma_bf16(acc[1], aH, bl4[2], bl4[3]);
                mma_bf16(acc[2], aH, bl2[0], bl2[1]);
                mma_bf16(acc[0], aL, bh4[0], bh4[1]);
                mma_bf16(acc[1], aL, bh4[2], bh4[3]);
                mma_bf16(acc[2], aL, bh2[0], bh2[1]);
            }
            __syncthreads();
        }

        // ---- write fragments to sG[64][52] ----
        #pragma unroll
        for (int f = 0; f < 3; f++) {
            const int cb = nv * 24 + f * 8 + (lane & 3) * 2;
            sG[r_base * 52 + cb]           = acc[f][0];
            sG[r_base * 52 + cb + 1]       = acc[f][1];
            sG[(r_base + 8) * 52 + cb]     = acc[f][2];
            sG[(r_base + 8) * 52 + cb + 1] = acc[f][3];
        }
        __syncthreads();

        // ---- gate epilogue ----
        {
            __nv_bfloat16* dstH = hh_base + (size_t)((t + 1) & 1) * BB * HH;
            __nv_bfloat16* dstL = hl_base + (size_t)((t + 1) & 1) * BB * HH;
            float* hout = hist + (size_t)t * BB * HH;
            #pragma unroll
            for (int n = 0; n < 2; n++) {
                const int e = tid + THR * n;
                const int b = e >> 3, j = e & 7;
                const float hr = sG[b * 52 + 24 + j];
                const float hz = sG[b * 52 + 32 + j];
                const float hn = sG[b * 52 + 40 + j];
                float rv, zv, nn;
                if (t == 0) {
                    const int jg = jgv[n];
                    rv = sigmoidf_(g_gi0[jg] + hr + b_hh[jg]);
                    zv = sigmoidf_(g_gi0[HH + jg] + hz + b_hh[HH + jg]);
                    nn = tanhf(g_gi0[2 * HH + jg] + rv * (hn + b_hh[2 * HH + jg]));
                } else {
                    const float gr = sG[b * 52 + j];
                    const float gz = sG[b * 52 + 8 + j];
                    const float gn = sG[b * 52 + 16 + j];
                    rv = sigmoidf_(gr + hr + br_[n]);
                    zv = sigmoidf_(gz + hz + bz_[n]);
                    nn = tanhf(gn + bni_[n] + rv * (hn + bnh_[n]));
                }
                const float hv = (1.0f - zv) * nn + zv * hp[n];
                hp[n] = hv;
                hout[ooff[n]] = hv;
                const __nv_bfloat16 hi = __float2bfloat16(hv);
                dstH[ooff[n]] = hi;
                dstL[ooff[n]] = __float2bfloat16(hv - __bfloat162float(hi));
            }
        }
        __threadfence();

        #pragma unroll
        for (int f = 0; f < 3; f++)
            #pragma unroll
            for (int i = 0; i < 4; i++) acc[f][i] = 0.0f;

        __syncthreads();

        // ---- per-group grid barrier (fan-in 64; skip after final step) ----
        if (t < TT - 1) {
            if (tid == 0) {
                atomicAdd(&g_ctrs[bq], 1u);
                const unsigned int target = (unsigned int)(t + 1) * 64u;
                while (ld_acq(&g_ctrs[bq]) < target) {}
            }
            __syncthreads();
        }
    }
}

// ---------------------------------------------------------------------------
// Projection: out[b][v][t] = hist[t][b][:] . proj_w[v][:] + proj_b[v]
// ---------------------------------------------------------------------------
__global__ __launch_bounds__(512) void proj_kernel(
    const float* __restrict__ proj_w,
    const float* __restrict__ proj_b,
    float* __restrict__ out)
{
    __shared__ float sH[TT][33];
    __shared__ float sW[VV][33];

    const int b   = blockIdx.x;
    const int tid = threadIdx.x;
    const int tg  = tid % 25;
    const int vg  = tid / 25;
    const bool active = (tid < 500);

    float acc[8][5];
    #pragma unroll
    for (int i = 0; i < 8; i++)
        #pragma unroll
        for (int jv = 0; jv < 5; jv++) acc[i][jv] = 0.0f;

    for (int k0 = 0; k0 < HH; k0 += 32) {
        for (int idx = tid; idx < TT * 32; idx += 512) {
            const int t = idx >> 5, k = idx & 31;
            sH[t][k] = g_hist[((size_t)t * BB + b) * HH + k0 + k];
        }
        for (int idx = tid; idx < VV * 32; idx += 512) {
            const int v = idx >> 5, k = idx & 31;
            sW[v][k] = proj_w[(size_t)v * HH + k0 + k];
        }
        __syncthreads();

        if (active) {
            #pragma unroll
            for (int kk = 0; kk < 32; kk++) {
                float wv[5];
                #pragma unroll
                for (int jv = 0; jv < 5; jv++) wv[jv] = sW[vg * 5 + jv][kk];
                #pragma unroll
                for (int i = 0; i < 8; i++) {
                    const float hv = sH[tg + 25 * i][kk];
                    #pragma unroll
                    for (int jv = 0; jv < 5; jv++) acc[i][jv] += hv * wv[jv];
                }
            }
        }
        __syncthreads();
    }

    if (active) {
        float pb[5];
        #pragma unroll
        for (int jv = 0; jv < 5; jv++) pb[jv] = proj_b[vg * 5 + jv];
        #pragma unroll
        for (int i = 0; i < 8; i++) {
            const int t = tg + 25 * i;
            #pragma unroll
            for (int jv = 0; jv < 5; jv++) {
                const int v = vg * 5 + jv;
                out[((size_t)b * VV + v) * TT + t] = acc[i][jv] + pb[jv];
            }
        }
    }
}

// ---------------------------------------------------------------------------
extern "C" void kernel_launch(void* const* d_in, const int* in_sizes, int n_in,
                              void* d_out, int out_size)
{
    (void)in_sizes; (void)n_in; (void)out_size;
    const float* feat   = (const float*)d_in[0];
    const float* embed  = (const float*)d_in[1];
    const float* w_ih   = (const float*)d_in[2];
    const float* w_hh   = (const float*)d_in[3];
    const float* b_ih   = (const float*)d_in[4];
    const float* b_hh   = (const float*)d_in[5];
    const float* proj_w = (const float*)d_in[6];
    const float* proj_b = (const float*)d_in[7];
    float* out = (float*)d_out;

    float* hist = nullptr;
    cudaGetSymbolAddress((void**)&hist, g_hist);
    __nv_bfloat16* hhp = nullptr;
    cudaGetSymbolAddress((void**)&hhp, g_hh);
    __nv_bfloat16* hlp = nullptr;
    cudaGetSymbolAddress((void**)&hlp, g_hl);

    cudaFuncSetAttribute(gru_persistent,
                         cudaFuncAttributeMaxDynamicSharedMemorySize, SMEM_P);

    prep_weights<<<(6 * HH * HH + 255) / 256, 256>>>(w_ih, w_hh);
    reset_ctr_kernel<<<1, 32>>>();
    gi0_kernel<<<(3 * HH + 7) / 8, 256>>>(embed, w_ih, b_ih);
    convert_h<<<(BB * HH + 255) / 256, 256>>>(feat, hhp, hlp);   // feat -> slot 0

    // steps 0..199: persistent kernel, 256 blocks (2 CTAs/SM co-resident)
    gru_persistent<<<dim3(64, 4), THR, SMEM_P>>>(feat, b_ih, b_hh,
                                                 hist, hhp, hlp);

    proj_kernel<<<BB, 512>>>(proj_w, proj_b, out);
}

// round 16
// speedup vs baseline: 1.3299x; 1.1028x over previous
#include <cuda_runtime.h>
#include <cuda_bf16.h>
#include <stdint.h>
#include <math.h>

#define BB 256     // batch
#define HH 512     // hidden
#define VV 100     // vocab
#define TT 200     // steps

// fp32 hidden-state history
__device__ float g_hist[(size_t)TT * BB * HH];
// bf16 hi/lo ping-pong of h (slot = input slot for step t = t&1)
__device__ __nv_bfloat16 g_hh[2][BB * HH];
__device__ __nv_bfloat16 g_hl[2][BB * HH];
// packed weights: row n = jb*96 + g*16 + j  (jb=0..31, g=0..5, j=0..15)
__device__ __nv_bfloat16 g_wh[6 * HH * HH];
__device__ __nv_bfloat16 g_wl[6 * HH * HH];
// precomputed x-side step-0 gates: gi0[row] = embed0 . w_ih[row] + b_ih[row]
__device__ float g_gi0[3 * HH];
// per-batch-group step barrier counters
__device__ unsigned int g_ctrs[4];

__device__ __forceinline__ float sigmoidf_(float x) {
    return 1.0f / (1.0f + expf(-x));
}

// ---------------------------------------------------------------------------
// async / mma / sync helpers
// ---------------------------------------------------------------------------
__device__ __forceinline__ void cp_async16(void* smem_dst, const void* gmem_src) {
    unsigned int s = (unsigned int)__cvta_generic_to_shared(smem_dst);
    asm volatile("cp.async.cg.shared.global [%0], [%1], 16;\n" :: "r"(s), "l"(gmem_src));
}
#define CP_COMMIT() asm volatile("cp.async.commit_group;\n" ::: "memory")
#define CP_WAIT(n)  asm volatile("cp.async.wait_group %0;\n" :: "n"(n) : "memory")

__device__ __forceinline__ void ldsm4(uint32_t r[4], const void* p) {
    unsigned int s = (unsigned int)__cvta_generic_to_shared(p);
    asm volatile("ldmatrix.sync.aligned.m8n8.x4.shared.b16 {%0,%1,%2,%3}, [%4];"
                 : "=r"(r[0]), "=r"(r[1]), "=r"(r[2]), "=r"(r[3]) : "r"(s));
}

__device__ __forceinline__ void mma_bf16(float d[4], const uint32_t a[4],
                                         uint32_t b0, uint32_t b1) {
    asm volatile(
        "mma.sync.aligned.m16n8k16.row.col.f32.bf16.bf16.f32 "
        "{%0,%1,%2,%3}, {%4,%5,%6,%7}, {%8,%9}, {%0,%1,%2,%3};"
        : "+f"(d[0]), "+f"(d[1]), "+f"(d[2]), "+f"(d[3])
        : "r"(a[0]), "r"(a[1]), "r"(a[2]), "r"(a[3]), "r"(b0), "r"(b1));
}

__device__ __forceinline__ unsigned int ld_acq(const unsigned int* p) {
    unsigned int v;
    asm volatile("ld.acquire.gpu.u32 %0, [%1];" : "=r"(v) : "l"(p));
    return v;
}

// ---------------------------------------------------------------------------
// One-time weight prep: pack + split fp32 -> bf16 hi/lo.
// ---------------------------------------------------------------------------
__global__ __launch_bounds__(256) void prep_weights(
    const float* __restrict__ w_ih, const float* __restrict__ w_hh)
{
    int idx = blockIdx.x * 256 + threadIdx.x;
    if (idx >= 6 * HH * HH) return;
    int n = idx / HH, k = idx % HH;
    int jb = n / 96, rr = n % 96, g = rr / 16, j = rr % 16;
    const float* src = (g < 3) ? w_ih : w_hh;
    float v = src[(size_t)((g % 3) * HH + jb * 16 + j) * HH + k];
    __nv_bfloat16 hi = __float2bfloat16(v);
    g_wh[idx] = hi;
    g_wl[idx] = __float2bfloat16(v - __bfloat162float(hi));
}

__global__ void reset_ctr_kernel() {
    if (threadIdx.x < 4) g_ctrs[threadIdx.x] = 0u;
}

// gi0[row] = embed[0,:] . w_ih[row,:] + b_ih[row]   (one warp per row)
__global__ __launch_bounds__(256) void gi0_kernel(
    const float* __restrict__ embed, const float* __restrict__ w_ih,
    const float* __restrict__ b_ih)
{
    const int row  = blockIdx.x * 8 + (threadIdx.x >> 5);
    const int lane = threadIdx.x & 31;
    if (row >= 3 * HH) return;
    float s = 0.0f;
    for (int k = lane; k < HH; k += 32)
        s += embed[k] * w_ih[(size_t)row * HH + k];
    #pragma unroll
    for (int o = 16; o; o >>= 1) s += __shfl_xor_sync(0xFFFFFFFFu, s, o);
    if (lane == 0) g_gi0[row] = s + b_ih[row];
}

// Convert fp32 vec -> bf16 hi/lo
__global__ __launch_bounds__(256) void convert_h(
    const float* __restrict__ h, __nv_bfloat16* __restrict__ hh,
    __nv_bfloat16* __restrict__ hl)
{
    int idx = blockIdx.x * 256 + threadIdx.x;
    if (idx >= BB * HH) return;
    float v = h[idx];
    __nv_bfloat16 hi = __float2bfloat16(v);
    hh[idx] = hi;
    hl[idx] = __float2bfloat16(v - __bfloat162float(hi));
}

// ---------------------------------------------------------------------------
// Persistent tensor-core GRU: EXACT R7 structure (measured best), with step 0
// folded in (x-gates from g_gi0; A source for t=0 is converted feat).
// Grid (32 jb, 4 bq) = 128 blocks, 384 threads (12 warps: 4 mw x 3 nv(n=32)).
// B tile (96x512, hi+lo) XOR-swizzled, SMEM-resident whole kernel.
// A (h hi/lo) streamed per step, k=64 chunks, double buffer.
// Step barrier: per-bq-group atomic counter (fan-in 32).
// ---------------------------------------------------------------------------
#define THR    384
#define B_MATS (96 * 512)                   // bf16 per B matrix (swizzled)
#define OFF_A  (2 * B_MATS)                 // 98304 bf16
#define A_MATS (64 * 64)                    // bf16 per A matrix per chunk
#define A_BUF  (2 * A_MATS)                 // hi+lo per buffer = 8192 bf16
#define SMEM_P ((OFF_A + 2 * A_BUF) * 2)    // 229376 bytes (224 KB)
#define NCH    8                            // K chunks of 64

__global__ __launch_bounds__(THR) void gru_persistent(
    const float* __restrict__ feat,
    const float* __restrict__ b_ih,
    const float* __restrict__ b_hh,
    float* __restrict__ hist,                 // [TT][BB][HH]
    __nv_bfloat16* __restrict__ hh_base,      // [2][BB*HH]
    __nv_bfloat16* __restrict__ hl_base)
{
    extern __shared__ __align__(16) __nv_bfloat16 dsm[];

    const int tid  = threadIdx.x;
    const int lane = tid & 31;
    const int w    = tid >> 5;           // 0..11
    const int mw   = w & 3;              // m16 tile
    const int nv   = w >> 2;             // 0..2, n=32 each
    const int jb   = blockIdx.x;         // 0..31
    const int bq   = blockIdx.y;         // 0..3
    const int b0   = bq * 64;

    // ================= resident B load (swizzled, once) =================
    for (int i = tid; i < 2 * 96 * 64; i += THR) {     // 16B granules
        const int mat = i / (96 * 64);
        const int rr  = i % (96 * 64);
        const int row = rr >> 6;
        const int g   = rr & 63;
        const int gs  = (g & 56) | ((g ^ row) & 7);
        const __nv_bfloat16* src =
            (mat ? g_wl : g_wh) + (size_t)(jb * 96 + row) * HH + g * 8;
        cp_async16(dsm + mat * B_MATS + row * 512 + gs * 8, src);
    }
    CP_COMMIT();

    // ========== per-thread A-chunk cp.async descriptors (<=3 each) =========
    int aMat[3], aDst[3], aSrc[3];
    #pragma unroll
    for (int k = 0; k < 3; k++) {
        const int i = tid + THR * k;
        if (i < 1024) {
            const int mat = i >> 9;
            const int r   = (i >> 3) & 63;
            const int g   = i & 7;
            aMat[k] = mat;
            aDst[k] = mat * A_MATS + r * 64 + ((g ^ (r & 7)) * 8);
            aSrc[k] = (b0 + r) * HH + g * 8;
        }
    }
    const bool a3 = (tid + 2 * THR < 1024);

    // ================= ldmatrix lane invariants =================
    const int a_row  = mw * 16 + (lane & 15);
    const int a_g0   = (lane >> 4);
    const int a_base = a_row * 64;
    const int a_r7   = a_row & 7;
    const int b_rowL = (lane & 7) + ((lane & 16) ? 8 : 0);
    const int b_g0   = (lane & 8) ? 1 : 0;
    int b_base[2], b_r7[2];
    #pragma unroll
    for (int p = 0; p < 2; p++) {
        const int brow = nv * 32 + p * 16 + b_rowL;
        b_base[p] = brow * 512;
        b_r7[p]   = brow & 7;
    }
    const int r_base = mw * 16 + (lane >> 2);

    // ================= epilogue per-thread state =================
    float hp[3], br_[3], bz_[3], bni_[3], bnh_[3];
    int   ooff[3], jgv[3];
    #pragma unroll
    for (int n = 0; n < 3; n++) {
        const int e = tid + THR * n;
        if (e < 1024) {
            const int b  = e >> 4;
            const int j  = e & 15;
            const int jg = jb * 16 + j;
            jgv[n]  = jg;
            ooff[n] = (b0 + b) * HH + jg;
            br_[n]  = b_ih[jg] + b_hh[jg];
            bz_[n]  = b_ih[HH + jg] + b_hh[HH + jg];
            bni_[n] = b_ih[2 * HH + jg];
            bnh_[n] = b_hh[2 * HH + jg];
            hp[n]   = feat[ooff[n]];          // h_prev for step 0
        }
    }

    CP_WAIT(0);
    __syncthreads();

    float acc[4][4];
    #pragma unroll
    for (int f = 0; f < 4; f++)
        #pragma unroll
        for (int i = 0; i < 4; i++) acc[f][i] = 0.0f;

    float* sG = (float*)(dsm + OFF_A);   // [64][100] gate exchange (aliases A)

    for (int t = 0; t < TT; t++) {
        const __nv_bfloat16* srcH = hh_base + (size_t)(t & 1) * BB * HH;
        const __nv_bfloat16* srcL = hl_base + (size_t)(t & 1) * BB * HH;

        // prologue: chunk 0 -> buf 0
        {
            __nv_bfloat16* buf = dsm + OFF_A;
            cp_async16(buf + aDst[0], (aMat[0] ? srcL : srcH) + aSrc[0]);
            cp_async16(buf + aDst[1], (aMat[1] ? srcL : srcH) + aSrc[1]);
            if (a3)
                cp_async16(buf + aDst[2], (aMat[2] ? srcL : srcH) + aSrc[2]);
            CP_COMMIT();
        }

        #pragma unroll 1
        for (int c = 0; c < NCH; c++) {
            if (c + 1 < NCH) {
                __nv_bfloat16* buf = dsm + OFF_A + ((c + 1) & 1) * A_BUF;
                const int k0 = (c + 1) * 64;
                cp_async16(buf + aDst[0], (aMat[0] ? srcL : srcH) + aSrc[0] + k0);
                cp_async16(buf + aDst[1], (aMat[1] ? srcL : srcH) + aSrc[1] + k0);
                if (a3)
                    cp_async16(buf + aDst[2], (aMat[2] ? srcL : srcH) + aSrc[2] + k0);
                CP_COMMIT();
                CP_WAIT(1);
            } else {
                CP_WAIT(0);
            }
            __syncthreads();

            const __nv_bfloat16* bufA = dsm + OFF_A + (c & 1) * A_BUF;
            #pragma unroll
            for (int q = 0; q < 4; q++) {
                uint32_t aH[4], aL[4];
                const int gsA = ((2 * q + a_g0) ^ a_r7) * 8;
                ldsm4(aH, bufA + a_base + gsA);
                ldsm4(aL, bufA + A_MATS + a_base + gsA);
                const int gqB = c * 8 + 2 * q + b_g0;
                #pragma unroll
                for (int p = 0; p < 2; p++) {
                    const int gsB = (gqB & 56) | ((gqB ^ b_r7[p]) & 7);
                    const int off = b_base[p] + gsB * 8;
                    uint32_t bh[4], bl[4];
                    ldsm4(bh, dsm + off);
                    ldsm4(bl, dsm + B_MATS + off);
                    mma_bf16(acc[2 * p],     aH, bh[0], bh[1]);
                    mma_bf16(acc[2 * p],     aH, bl[0], bl[1]);
                    mma_bf16(acc[2 * p],     aL, bh[0], bh[1]);
                    mma_bf16(acc[2 * p + 1], aH, bh[2], bh[3]);
                    mma_bf16(acc[2 * p + 1], aH, bl[2], bl[3]);
                    mma_bf16(acc[2 * p + 1], aL, bh[2], bh[3]);
                }
            }
            __syncthreads();   // buffer consumed (and pre-sG for last chunk)
        }

        // ---- write fragments to sG[64][100] ----
        {
            #pragma unroll
            for (int f = 0; f < 4; f++) {
                const int cb = nv * 32 + f * 8 + (lane & 3) * 2;
                sG[r_base * 100 + cb]           = acc[f][0];
                sG[r_base * 100 + cb + 1]       = acc[f][1];
                sG[(r_base + 8) * 100 + cb]     = acc[f][2];
                sG[(r_base + 8) * 100 + cb + 1] = acc[f][3];
            }
        }
        __syncthreads();

        // ---- gate epilogue ----
        {
            __nv_bfloat16* dstH = hh_base + (size_t)((t + 1) & 1) * BB * HH;
            __nv_bfloat16* dstL = hl_base + (size_t)((t + 1) & 1) * BB * HH;
            float* hout = hist + (size_t)t * BB * HH;
            #pragma unroll
            for (int n = 0; n < 3; n++) {
                const int e = tid + THR * n;
                if (e < 1024) {
                    const int b = e >> 4, j = e & 15;
                    const float hr = sG[b * 100 + 48 + j];
                    const float hz = sG[b * 100 + 64 + j];
                    const float hn = sG[b * 100 + 80 + j];
                    float rv, zv, nn;
                    if (t == 0) {
                        const int jg = jgv[n];
                        rv = sigmoidf_(g_gi0[jg] + hr + b_hh[jg]);
                        zv = sigmoidf_(g_gi0[HH + jg] + hz + b_hh[HH + jg]);
                        nn = tanhf(g_gi0[2 * HH + jg]
                                   + rv * (hn + b_hh[2 * HH + jg]));
                    } else {
                        const float gr = sG[b * 100 + j];
                        const float gz = sG[b * 100 + 16 + j];
                        const float gn = sG[b * 100 + 32 + j];
                        rv = sigmoidf_(gr + hr + br_[n]);
                        zv = sigmoidf_(gz + hz + bz_[n]);
                        nn = tanhf(gn + bni_[n] + rv * (hn + bnh_[n]));
                    }
                    const float hv = (1.0f - zv) * nn + zv * hp[n];
                    hp[n] = hv;
                    hout[ooff[n]] = hv;
                    const __nv_bfloat16 hi = __float2bfloat16(hv);
                    dstH[ooff[n]] = hi;
                    dstL[ooff[n]] = __float2bfloat16(hv - __bfloat162float(hi));
                }
            }
        }
        __threadfence();

        // reset accumulators
        #pragma unroll
        for (int f = 0; f < 4; f++)
            #pragma unroll
            for (int i = 0; i < 4; i++) acc[f][i] = 0.0f;

        __syncthreads();   // epilogue stores + sG reads done

        // ---- per-group grid barrier (skip after final step) ----
        if (t < TT - 1) {
            if (tid == 0) {
                atomicAdd(&g_ctrs[bq], 1u);
                const unsigned int target = (unsigned int)(t + 1) * 32u;
                unsigned int v;
                do {
                    v = ld_acq(&g_ctrs[bq]);
                } while (v < target);
            }
            __syncthreads();
        }
    }
}

// ---------------------------------------------------------------------------
// Projection: out[b][v][t] = hist[t][b][:] . proj_w[v][:] + proj_b[v]
// ---------------------------------------------------------------------------
__global__ __launch_bounds__(512) void proj_kernel(
    const float* __restrict__ proj_w,
    const float* __restrict__ proj_b,
    float* __restrict__ out)
{
    __shared__ float sH[TT][33];
    __shared__ float sW[VV][33];

    const int b   = blockIdx.x;
    const int tid = threadIdx.x;
    const int tg  = tid % 25;
    const int vg  = tid / 25;
    const bool active = (tid < 500);

    float acc[8][5];
    #pragma unroll
    for (int i = 0; i < 8; i++)
        #pragma unroll
        for (int jv = 0; jv < 5; jv++) acc[i][jv] = 0.0f;

    for (int k0 = 0; k0 < HH; k0 += 32) {
        for (int idx = tid; idx < TT * 32; idx += 512) {
            const int t = idx >> 5, k = idx & 31;
            sH[t][k] = g_hist[((size_t)t * BB + b) * HH + k0 + k];
        }
        for (int idx = tid; idx < VV * 32; idx += 512) {
            const int v = idx >> 5, k = idx & 31;
            sW[v][k] = proj_w[(size_t)v * HH + k0 + k];
        }
        __syncthreads();

        if (active) {
            #pragma unroll
            for (int kk = 0; kk < 32; kk++) {
                float wv[5];
                #pragma unroll
                for (int jv = 0; jv < 5; jv++) wv[jv] = sW[vg * 5 + jv][kk];
                #pragma unroll
                for (int i = 0; i < 8; i++) {
                    const float hv = sH[tg + 25 * i][kk];
                    #pragma unroll
                    for (int jv = 0; jv < 5; jv++) acc[i][jv] += hv * wv[jv];
                }
            }
        }
        __syncthreads();
    }

    if (active) {
        float pb[5];
        #pragma unroll
        for (int jv = 0; jv < 5; jv++) pb[jv] = proj_b[vg * 5 + jv];
        #pragma unroll
        for (int i = 0; i < 8; i++) {
            const int t = tg + 25 * i;
            #pragma unroll
            for (int jv = 0; jv < 5; jv++) {
                const int v = vg * 5 + jv;
                out[((size_t)b * VV + v) * TT + t] = acc[i][jv] + pb[jv];
            }
        }
    }
}

// ---------------------------------------------------------------------------
extern "C" void kernel_launch(void* const* d_in, const int* in_sizes, int n_in,
                              void* d_out, int out_size)
{
    (void)in_sizes; (void)n_in; (void)out_size;
    const float* feat   = (const float*)d_in[0];
    const float* embed  = (const float*)d_in[1];
    const float* w_ih   = (const float*)d_in[2];
    const float* w_hh   = (const float*)d_in[3];
    const float* b_ih   = (const float*)d_in[4];
    const float* b_hh   = (const float*)d_in[5];
    const float* proj_w = (const float*)d_in[6];
    const float* proj_b = (const float*)d_in[7];
    float* out = (float*)d_out;

    float* hist = nullptr;
    cudaGetSymbolAddress((void**)&hist, g_hist);
    __nv_bfloat16* hhp = nullptr;
    cudaGetSymbolAddress((void**)&hhp, g_hh);
    __nv_bfloat16* hlp = nullptr;
    cudaGetSymbolAddress((void**)&hlp, g_hl);

    cudaFuncSetAttribute(gru_persistent,
                         cudaFuncAttributeMaxDynamicSharedMemorySize, SMEM_P);

    prep_weights<<<(6 * HH * HH + 255) / 256, 256>>>(w_ih, w_hh);
    reset_ctr_kernel<<<1, 32>>>();
    gi0_kernel<<<(3 * HH + 7) / 8, 256>>>(embed, w_ih, b_ih);
    convert_h<<<(BB * HH + 255) / 256, 256>>>(feat, hhp, hlp);   // feat -> slot 0

    // steps 0..199 in one persistent kernel (one wave of 128 blocks)
    gru_persistent<<<dim3(32, 4), THR, SMEM_P>>>(feat, b_ih, b_hh,
                                                 hist, hhp, hlp);

    proj_kernel<<<BB, 512>>>(proj_w, proj_b, out);
}

// round 17
// speedup vs baseline: 1.5098x; 1.1353x over previous
#include <cuda_runtime.h>
#include <cuda_bf16.h>
#include <stdint.h>
#include <math.h>

#define BB 256     // batch
#define HH 512     // hidden
#define VV 100     // vocab
#define TT 200     // steps

// bf16 hi/lo hidden history: slot 0 = feat, slot t+1 = h_t  (201 slots)
__device__ __nv_bfloat16 g_hhist[(size_t)(TT + 1) * BB * HH];
__device__ __nv_bfloat16 g_lhist[(size_t)(TT + 1) * BB * HH];
// packed GRU weights: row n = jb*96 + g*16 + j  (jb=0..31, g=0..5, j=0..15)
__device__ __nv_bfloat16 g_wh[6 * HH * HH];
__device__ __nv_bfloat16 g_wl[6 * HH * HH];
// packed projection weights, padded to 128 rows (rows >= VV are zero)
__device__ __nv_bfloat16 g_pwh[128 * HH];
__device__ __nv_bfloat16 g_pwl[128 * HH];
// precomputed x-side step-0 gates
__device__ float g_gi0[3 * HH];
// per-batch-group step barrier counters
__device__ unsigned int g_ctrs[4];

__device__ __forceinline__ float sigmoidf_(float x) {
    return 1.0f / (1.0f + expf(-x));
}

// ---------------------------------------------------------------------------
// async / mma / sync helpers
// ---------------------------------------------------------------------------
__device__ __forceinline__ void cp_async16(void* smem_dst, const void* gmem_src) {
    unsigned int s = (unsigned int)__cvta_generic_to_shared(smem_dst);
    asm volatile("cp.async.cg.shared.global [%0], [%1], 16;\n" :: "r"(s), "l"(gmem_src));
}
#define CP_COMMIT() asm volatile("cp.async.commit_group;\n" ::: "memory")
#define CP_WAIT(n)  asm volatile("cp.async.wait_group %0;\n" :: "n"(n) : "memory")

__device__ __forceinline__ void ldsm4(uint32_t r[4], const void* p) {
    unsigned int s = (unsigned int)__cvta_generic_to_shared(p);
    asm volatile("ldmatrix.sync.aligned.m8n8.x4.shared.b16 {%0,%1,%2,%3}, [%4];"
                 : "=r"(r[0]), "=r"(r[1]), "=r"(r[2]), "=r"(r[3]) : "r"(s));
}
__device__ __forceinline__ void ldsm2(uint32_t r[2], const void* p) {
    unsigned int s = (unsigned int)__cvta_generic_to_shared(p);
    asm volatile("ldmatrix.sync.aligned.m8n8.x2.shared.b16 {%0,%1}, [%2];"
                 : "=r"(r[0]), "=r"(r[1]) : "r"(s));
}

__device__ __forceinline__ void mma_bf16(float d[4], const uint32_t a[4],
                                         uint32_t b0, uint32_t b1) {
    asm volatile(
        "mma.sync.aligned.m16n8k16.row.col.f32.bf16.bf16.f32 "
        "{%0,%1,%2,%3}, {%4,%5,%6,%7}, {%8,%9}, {%0,%1,%2,%3};"
        : "+f"(d[0]), "+f"(d[1]), "+f"(d[2]), "+f"(d[3])
        : "r"(a[0]), "r"(a[1]), "r"(a[2]), "r"(a[3]), "r"(b0), "r"(b1));
}

__device__ __forceinline__ unsigned int ld_acq(const unsigned int* p) {
    unsigned int v;
    asm volatile("ld.acquire.gpu.u32 %0, [%1];" : "=r"(v) : "l"(p));
    return v;
}

// ---------------------------------------------------------------------------
// One-time weight prep kernels
// ---------------------------------------------------------------------------
__global__ __launch_bounds__(256) void prep_weights(
    const float* __restrict__ w_ih, const float* __restrict__ w_hh)
{
    int idx = blockIdx.x * 256 + threadIdx.x;
    if (idx >= 6 * HH * HH) return;
    int n = idx / HH, k = idx % HH;
    int jb = n / 96, rr = n % 96, g = rr / 16, j = rr % 16;
    const float* src = (g < 3) ? w_ih : w_hh;
    float v = src[(size_t)((g % 3) * HH + jb * 16 + j) * HH + k];
    __nv_bfloat16 hi = __float2bfloat16(v);
    g_wh[idx] = hi;
    g_wl[idx] = __float2bfloat16(v - __bfloat162float(hi));
}

__global__ __launch_bounds__(256) void prep_pw(const float* __restrict__ proj_w)
{
    int idx = blockIdx.x * 256 + threadIdx.x;
    if (idx >= 128 * HH) return;
    int row = idx >> 9, k = idx & 511;
    float v = (row < VV) ? proj_w[(size_t)row * HH + k] : 0.0f;
    __nv_bfloat16 hi = __float2bfloat16(v);
    g_pwh[idx] = hi;
    g_pwl[idx] = __float2bfloat16(v - __bfloat162float(hi));
}

__global__ void reset_ctr_kernel() {
    if (threadIdx.x < 4) g_ctrs[threadIdx.x] = 0u;
}

// gi0[row] = embed[0,:] . w_ih[row,:] + b_ih[row]
__global__ __launch_bounds__(256) void gi0_kernel(
    const float* __restrict__ embed, const float* __restrict__ w_ih,
    const float* __restrict__ b_ih)
{
    const int row  = blockIdx.x * 8 + (threadIdx.x >> 5);
    const int lane = threadIdx.x & 31;
    if (row >= 3 * HH) return;
    float s = 0.0f;
    for (int k = lane; k < HH; k += 32)
        s += embed[k] * w_ih[(size_t)row * HH + k];
    #pragma unroll
    for (int o = 16; o; o >>= 1) s += __shfl_xor_sync(0xFFFFFFFFu, s, o);
    if (lane == 0) g_gi0[row] = s + b_ih[row];
}

// feat -> history slot 0 (hi/lo)
__global__ __launch_bounds__(256) void convert_h(const float* __restrict__ h)
{
    int idx = blockIdx.x * 256 + threadIdx.x;
    if (idx >= BB * HH) return;
    float v = h[idx];
    __nv_bfloat16 hi = __float2bfloat16(v);
    g_hhist[idx] = hi;
    g_lhist[idx] = __float2bfloat16(v - __bfloat162float(hi));
}

// ---------------------------------------------------------------------------
// Persistent tensor-core GRU: EXACT R7/R16 structure; history addressing only.
// Grid (32 jb, 4 bq) = 128 blocks, 384 threads (12 warps: 4 mw x 3 nv(n=32)).
// ---------------------------------------------------------------------------
#define THR    384
#define B_MATS (96 * 512)
#define OFF_A  (2 * B_MATS)
#define A_MATS (64 * 64)
#define A_BUF  (2 * A_MATS)
#define SMEM_P ((OFF_A + 2 * A_BUF) * 2)    // 229376 bytes
#define NCH    8

__global__ __launch_bounds__(THR) void gru_persistent(
    const float* __restrict__ feat,
    const float* __restrict__ b_ih,
    const float* __restrict__ b_hh,
    __nv_bfloat16* __restrict__ hh_hist,      // [(TT+1)][BB*HH]
    __nv_bfloat16* __restrict__ hl_hist)
{
    extern __shared__ __align__(16) __nv_bfloat16 dsm[];

    const int tid  = threadIdx.x;
    const int lane = tid & 31;
    const int w    = tid >> 5;
    const int mw   = w & 3;
    const int nv   = w >> 2;
    const int jb   = blockIdx.x;
    const int bq   = blockIdx.y;
    const int b0   = bq * 64;

    // resident B load (swizzled, once)
    for (int i = tid; i < 2 * 96 * 64; i += THR) {
        const int mat = i / (96 * 64);
        const int rr  = i % (96 * 64);
        const int row = rr >> 6;
        const int g   = rr & 63;
        const int gs  = (g & 56) | ((g ^ row) & 7);
        const __nv_bfloat16* src =
            (mat ? g_wl : g_wh) + (size_t)(jb * 96 + row) * HH + g * 8;
        cp_async16(dsm + mat * B_MATS + row * 512 + gs * 8, src);
    }
    CP_COMMIT();

    int aMat[3], aDst[3], aSrc[3];
    #pragma unroll
    for (int k = 0; k < 3; k++) {
        const int i = tid + THR * k;
        if (i < 1024) {
            const int mat = i >> 9;
            const int r   = (i >> 3) & 63;
            const int g   = i & 7;
            aMat[k] = mat;
            aDst[k] = mat * A_MATS + r * 64 + ((g ^ (r & 7)) * 8);
            aSrc[k] = (b0 + r) * HH + g * 8;
        }
    }
    const bool a3 = (tid + 2 * THR < 1024);

    const int a_row  = mw * 16 + (lane & 15);
    const int a_g0   = (lane >> 4);
    const int a_base = a_row * 64;
    const int a_r7   = a_row & 7;
    const int b_rowL = (lane & 7) + ((lane & 16) ? 8 : 0);
    const int b_g0   = (lane & 8) ? 1 : 0;
    int b_base[2], b_r7[2];
    #pragma unroll
    for (int p = 0; p < 2; p++) {
        const int brow = nv * 32 + p * 16 + b_rowL;
        b_base[p] = brow * 512;
        b_r7[p]   = brow & 7;
    }
    const int r_base = mw * 16 + (lane >> 2);

    float hp[3], br_[3], bz_[3], bni_[3], bnh_[3];
    int   ooff[3], jgv[3];
    #pragma unroll
    for (int n = 0; n < 3; n++) {
        const int e = tid + THR * n;
        if (e < 1024) {
            const int b  = e >> 4;
            const int j  = e & 15;
            const int jg = jb * 16 + j;
            jgv[n]  = jg;
            ooff[n] = (b0 + b) * HH + jg;
            br_[n]  = b_ih[jg] + b_hh[jg];
            bz_[n]  = b_ih[HH + jg] + b_hh[HH + jg];
            bni_[n] = b_ih[2 * HH + jg];
            bnh_[n] = b_hh[2 * HH + jg];
            hp[n]   = feat[ooff[n]];
        }
    }

    CP_WAIT(0);
    __syncthreads();

    float acc[4][4];
    #pragma unroll
    for (int f = 0; f < 4; f++)
        #pragma unroll
        for (int i = 0; i < 4; i++) acc[f][i] = 0.0f;

    float* sG = (float*)(dsm + OFF_A);

    for (int t = 0; t < TT; t++) {
        const __nv_bfloat16* srcH = hh_hist + (size_t)t * BB * HH;
        const __nv_bfloat16* srcL = hl_hist + (size_t)t * BB * HH;

        {
            __nv_bfloat16* buf = dsm + OFF_A;
            cp_async16(buf + aDst[0], (aMat[0] ? srcL : srcH) + aSrc[0]);
            cp_async16(buf + aDst[1], (aMat[1] ? srcL : srcH) + aSrc[1]);
            if (a3)
                cp_async16(buf + aDst[2], (aMat[2] ? srcL : srcH) + aSrc[2]);
            CP_COMMIT();
        }

        #pragma unroll 1
        for (int c = 0; c < NCH; c++) {
            if (c + 1 < NCH) {
                __nv_bfloat16* buf = dsm + OFF_A + ((c + 1) & 1) * A_BUF;
                const int k0 = (c + 1) * 64;
                cp_async16(buf + aDst[0], (aMat[0] ? srcL : srcH) + aSrc[0] + k0);
                cp_async16(buf + aDst[1], (aMat[1] ? srcL : srcH) + aSrc[1] + k0);
                if (a3)
                    cp_async16(buf + aDst[2], (aMat[2] ? srcL : srcH) + aSrc[2] + k0);
                CP_COMMIT();
                CP_WAIT(1);
            } else {
                CP_WAIT(0);
            }
            __syncthreads();

            const __nv_bfloat16* bufA = dsm + OFF_A + (c & 1) * A_BUF;
            #pragma unroll
            for (int q = 0; q < 4; q++) {
                uint32_t aH[4], aL[4];
                const int gsA = ((2 * q + a_g0) ^ a_r7) * 8;
                ldsm4(aH, bufA + a_base + gsA);
                ldsm4(aL, bufA + A_MATS + a_base + gsA);
                const int gqB = c * 8 + 2 * q + b_g0;
                #pragma unroll
                for (int p = 0; p < 2; p++) {
                    const int gsB = (gqB & 56) | ((gqB ^ b_r7[p]) & 7);
                    const int off = b_base[p] + gsB * 8;
                    uint32_t bh[4], bl[4];
                    ldsm4(bh, dsm + off);
                    ldsm4(bl, dsm + B_MATS + off);
                    mma_bf16(acc[2 * p],     aH, bh[0], bh[1]);
                    mma_bf16(acc[2 * p],     aH, bl[0], bl[1]);
                    mma_bf16(acc[2 * p],     aL, bh[0], bh[1]);
                    mma_bf16(acc[2 * p + 1], aH, bh[2], bh[3]);
                    mma_bf16(acc[2 * p + 1], aH, bl[2], bl[3]);
                    mma_bf16(acc[2 * p + 1], aL, bh[2], bh[3]);
                }
            }
            __syncthreads();
        }

        {
            #pragma unroll
            for (int f = 0; f < 4; f++) {
                const int cb = nv * 32 + f * 8 + (lane & 3) * 2;
                sG[r_base * 100 + cb]           = acc[f][0];
                sG[r_base * 100 + cb + 1]       = acc[f][1];
                sG[(r_base + 8) * 100 + cb]     = acc[f][2];
                sG[(r_base + 8) * 100 + cb + 1] = acc[f][3];
            }
        }
        __syncthreads();

        {
            __nv_bfloat16* dstH = hh_hist + (size_t)(t + 1) * BB * HH;
            __nv_bfloat16* dstL = hl_hist + (size_t)(t + 1) * BB * HH;
            #pragma unroll
            for (int n = 0; n < 3; n++) {
                const int e = tid + THR * n;
                if (e < 1024) {
                    const int b = e >> 4, j = e & 15;
                    const float hr = sG[b * 100 + 48 + j];
                    const float hz = sG[b * 100 + 64 + j];
                    const float hn = sG[b * 100 + 80 + j];
                    float rv, zv, nn;
                    if (t == 0) {
                        const int jg = jgv[n];
                        rv = sigmoidf_(g_gi0[jg] + hr + b_hh[jg]);
                        zv = sigmoidf_(g_gi0[HH + jg] + hz + b_hh[HH + jg]);
                        nn = tanhf(g_gi0[2 * HH + jg]
                                   + rv * (hn + b_hh[2 * HH + jg]));
                    } else {
                        const float gr = sG[b * 100 + j];
                        const float gz = sG[b * 100 + 16 + j];
                        const float gn = sG[b * 100 + 32 + j];
                        rv = sigmoidf_(gr + hr + br_[n]);
                        zv = sigmoidf_(gz + hz + bz_[n]);
                        nn = tanhf(gn + bni_[n] + rv * (hn + bnh_[n]));
                    }
                    const float hv = (1.0f - zv) * nn + zv * hp[n];
                    hp[n] = hv;
                    const __nv_bfloat16 hi = __float2bfloat16(hv);
                    dstH[ooff[n]] = hi;
                    dstL[ooff[n]] = __float2bfloat16(hv - __bfloat162float(hi));
                }
            }
        }
        __threadfence();

        #pragma unroll
        for (int f = 0; f < 4; f++)
            #pragma unroll
            for (int i = 0; i < 4; i++) acc[f][i] = 0.0f;

        __syncthreads();

        if (t < TT - 1) {
            if (tid == 0) {
                atomicAdd(&g_ctrs[bq], 1u);
                const unsigned int target = (unsigned int)(t + 1) * 32u;
                unsigned int v;
                do {
                    v = ld_acq(&g_ctrs[bq]);
                } while (v < target);
            }
            __syncthreads();
        }
    }
}

// ---------------------------------------------------------------------------
// HMMA projection: per-b GEMM  out[b, v, t] = W[v,:] . h_t[b,:] + pb[v]
// A = padded W (128 x 512) hi/lo, B = hist rows t (bf16 hi/lo), 3-term split.
// Grid 256 blocks (one per b), 512 threads (16 warps: 8 mw(m16) x 2 nv(n=104)).
// K chunked by 64, double buffered, XOR-swizzled 64-wide rows.
// ---------------------------------------------------------------------------
#define PTHR    512
#define PA_MAT  (128 * 64)
#define PA_BUF  (2 * PA_MAT)
#define PB_MAT  (208 * 64)
#define PB_BUF  (2 * PB_MAT)
#define POFF_B  (2 * PA_BUF)
#define PSMEM   ((2 * PA_BUF + 2 * PB_BUF) * 2)   // 172032 bytes

__global__ __launch_bounds__(PTHR) void proj_mma(
    const float* __restrict__ proj_b,
    float* __restrict__ out)                      // [B, V, T]
{
    extern __shared__ __align__(16) __nv_bfloat16 pdsm[];

    const int tid  = threadIdx.x;
    const int lane = tid & 31;
    const int w    = tid >> 5;          // 0..15
    const int mw   = w & 7;             // m16 tile 0..7
    const int nv   = w >> 3;            // 0..1
    const int b    = blockIdx.x;

    // A (W) granules: 2048/chunk, 4 per thread
    int aMat[4], aDst[4], aSrc[4];
    #pragma unroll
    for (int n = 0; n < 4; n++) {
        const int idx = tid + PTHR * n;     // 0..2047
        const int mat = idx >> 10;
        const int r   = (idx >> 3) & 127;
        const int g   = idx & 7;
        aMat[n] = mat;
        aDst[n] = mat * PA_MAT + r * 64 + ((g ^ (r & 7)) * 8);
        aSrc[n] = r * HH + g * 8;
    }
    // B (hist) granules: 3200/chunk, up to 7 per thread
    int bMat[7], bDst[7], bSrc[7];
    bool bOk[7];
    #pragma unroll
    for (int n = 0; n < 7; n++) {
        const int idx = tid + PTHR * n;     // < 3200
        bOk[n] = (idx < 3200);
        if (bOk[n]) {
            const int mat = idx / 1600;
            const int rr  = idx % 1600;
            const int r   = rr >> 3;        // t row 0..199
            const int g   = rr & 7;
            bMat[n] = mat;
            bDst[n] = POFF_B + mat * PB_MAT + r * 64 + ((g ^ (r & 7)) * 8);
            bSrc[n] = ((r + 1) * BB + b) * HH + g * 8;   // hist slot t+1
        }
    }

    // ldsm lane invariants
    const int a_row  = mw * 16 + (lane & 15);
    const int a_g0   = lane >> 4;
    const int a_base = a_row * 64;
    const int a_r7   = a_row & 7;
    const int b_g0   = (lane & 8) ? 1 : 0;
    int pb_base[6], pb_r7[6];
    #pragma unroll
    for (int p = 0; p < 6; p++) {
        const int brow = nv * 104 + p * 16 + (lane & 7) + ((lane & 16) ? 8 : 0);
        pb_base[p] = POFF_B + brow * 64;
        pb_r7[p]   = brow & 7;
    }
    const int brow2 = nv * 104 + 96 + (lane & 7);
    const int b2_base = POFF_B + brow2 * 64;
    const int b2_r7   = brow2 & 7;

    float acc[13][4];
    #pragma unroll
    for (int f = 0; f < 13; f++)
        #pragma unroll
        for (int i = 0; i < 4; i++) acc[f][i] = 0.0f;

    // prologue: chunk 0
    {
        __nv_bfloat16* buf = pdsm;
        #pragma unroll
        for (int n = 0; n < 4; n++)
            cp_async16(buf + aDst[n], (aMat[n] ? g_pwl : g_pwh) + aSrc[n]);
        #pragma unroll
        for (int n = 0; n < 7; n++)
            if (bOk[n])
                cp_async16(buf + bDst[n],
                           (bMat[n] ? g_lhist : g_hhist) + bSrc[n]);
        CP_COMMIT();
    }

    #pragma unroll 1
    for (int c = 0; c < 8; c++) {
        if (c + 1 < 8) {
            __nv_bfloat16* buf = pdsm + ((c + 1) & 1) * 0;  // base; offsets below
            const int bo = ((c + 1) & 1);
            const int k0 = (c + 1) * 64;
            #pragma unroll
            for (int n = 0; n < 4; n++)
                cp_async16(pdsm + bo * PA_BUF + aDst[n],
                           (aMat[n] ? g_pwl : g_pwh) + aSrc[n] + k0);
            #pragma unroll
            for (int n = 0; n < 7; n++)
                if (bOk[n])
                    cp_async16(pdsm + bo * PB_BUF + bDst[n],
                               (bMat[n] ? g_lhist : g_hhist) + bSrc[n] + k0);
            (void)buf;
            CP_COMMIT();
            CP_WAIT(1);
        } else {
            CP_WAIT(0);
        }
        __syncthreads();

        const int bo = c & 1;
        const __nv_bfloat16* bufA = pdsm + bo * PA_BUF;
        const __nv_bfloat16* bufB = pdsm + bo * PB_BUF;
        #pragma unroll
        for (int q = 0; q < 4; q++) {
            uint32_t aH[4], aL[4];
            const int gsA = ((2 * q + a_g0) ^ a_r7) * 8;
            ldsm4(aH, bufA + a_base + gsA);
            ldsm4(aL, bufA + PA_MAT + a_base + gsA);
            #pragma unroll
            for (int p = 0; p < 6; p++) {
                const int gs = ((2 * q + b_g0) ^ pb_r7[p]) * 8;
                uint32_t bh[4], bl[4];
                ldsm4(bh, bufB + pb_base[p] + gs);
                ldsm4(bl, bufB + PB_MAT + pb_base[p] + gs);
                mma_bf16(acc[2 * p],     aH, bh[0], bh[1]);
                mma_bf16(acc[2 * p],     aH, bl[0], bl[1]);
                mma_bf16(acc[2 * p],     aL, bh[0], bh[1]);
                mma_bf16(acc[2 * p + 1], aH, bh[2], bh[3]);
                mma_bf16(acc[2 * p + 1], aH, bl[2], bl[3]);
                mma_bf16(acc[2 * p + 1], aL, bh[2], bh[3]);
            }
            {
                const int gs = ((2 * q + b_g0) ^ b2_r7) * 8;
                uint32_t bh[2], bl[2];
                ldsm2(bh, bufB + b2_base + gs);
                ldsm2(bl, bufB + PB_MAT + b2_base + gs);
                mma_bf16(acc[12], aH, bh[0], bh[1]);
                mma_bf16(acc[12], aH, bl[0], bl[1]);
                mma_bf16(acc[12], aL, bh[0], bh[1]);
            }
        }
        __syncthreads();
    }

    // ---- store: out[b, v, t] (+ bias); t pairs contiguous -> float2 ----
    const int v0 = mw * 16 + (lane >> 2);
    const int v1 = v0 + 8;
    const float pb0 = (v0 < VV) ? proj_b[v0] : 0.0f;
    const float pb1 = (v1 < VV) ? proj_b[v1] : 0.0f;
    float* outb = out + (size_t)b * VV * TT;
    #pragma unroll
    for (int f = 0; f < 13; f++) {
        const int t = nv * 104 + f * 8 + (lane & 3) * 2;
        if (t < TT) {
            if (v0 < VV)
                *(float2*)(outb + (size_t)v0 * TT + t) =
                    make_float2(acc[f][0] + pb0, acc[f][1] + pb0);
            if (v1 < VV)
                *(float2*)(outb + (size_t)v1 * TT + t) =
                    make_float2(acc[f][2] + pb1, acc[f][3] + pb1);
        }
    }
}

// ---------------------------------------------------------------------------
extern "C" void kernel_launch(void* const* d_in, const int* in_sizes, int n_in,
                              void* d_out, int out_size)
{
    (void)in_sizes; (void)n_in; (void)out_size;
    const float* feat   = (const float*)d_in[0];
    const float* embed  = (const float*)d_in[1];
    const float* w_ih   = (const float*)d_in[2];
    const float* w_hh   = (const float*)d_in[3];
    const float* b_ih   = (const float*)d_in[4];
    const float* b_hh   = (const float*)d_in[5];
    const float* proj_w = (const float*)d_in[6];
    const float* proj_b = (const float*)d_in[7];
    float* out = (float*)d_out;

    __nv_bfloat16* hhp = nullptr;
    cudaGetSymbolAddress((void**)&hhp, g_hhist);
    __nv_bfloat16* hlp = nullptr;
    cudaGetSymbolAddress((void**)&hlp, g_lhist);

    cudaFuncSetAttribute(gru_persistent,
                         cudaFuncAttributeMaxDynamicSharedMemorySize, SMEM_P);
    cudaFuncSetAttribute(proj_mma,
                         cudaFuncAttributeMaxDynamicSharedMemorySize, PSMEM);

    prep_weights<<<(6 * HH * HH + 255) / 256, 256>>>(w_ih, w_hh);
    prep_pw<<<(128 * HH + 255) / 256, 256>>>(proj_w);
    reset_ctr_kernel<<<1, 32>>>();
    gi0_kernel<<<(3 * HH + 7) / 8, 256>>>(embed, w_ih, b_ih);
    convert_h<<<(BB * HH + 255) / 256, 256>>>(feat);   // feat -> slot 0

    // steps 0..199 in one persistent kernel (one wave of 128 blocks)
    gru_persistent<<<dim3(32, 4), THR, SMEM_P>>>(feat, b_ih, b_hh, hhp, hlp);

    // HMMA projection
    proj_mma<<<BB, PTHR, PSMEM>>>(proj_b, out);
}